// round 2
// baseline (speedup 1.0000x reference)
#include <cuda_runtime.h>
#include <cstdint>

#define NBR   19
#define DIMF  768
#define DD    384
#define BSZ   4096
#define XROW  (NBR * DIMF)   // 14592

// ---------------- scratch (device globals; no allocation allowed) ----------------
__device__ float g_fea_u[(size_t)BSZ * DIMF];
__device__ float g_h1[(size_t)BSZ * DD];
__device__ float g_fea_z[(size_t)BSZ * DD];
__device__ float g_vec[(size_t)NBR * BSZ * DD];
__device__ float g_att[(size_t)NBR * BSZ * DIMF];
__device__ float g_fea_v[(size_t)BSZ * DIMF];
__device__ float g_hA[(size_t)BSZ * 128];
__device__ float g_hB[(size_t)BSZ * 32];

// ---------------- helpers ----------------
__device__ __forceinline__ uint32_t f2tf32(float x) {
    uint32_t u;
    asm volatile("cvt.rna.tf32.f32 %0, %1;" : "=r"(u) : "f"(x));
    return u;
}
__device__ __forceinline__ void cp16(uint32_t dst, const void* src, int bytes) {
    asm volatile("cp.async.cg.shared.global [%0], [%1], 16, %2;\n"
                 :: "r"(dst), "l"(src), "r"(bytes));
}

// ---------------- generic tf32 NT GEMM: C[i][j] = sum_k A[i][k] * B[j][k] ----------------
// A split into two K-segments (A0: K0 cols contiguous rows, A1: K1 cols with row stride lda1)
// to fuse concat([vec, g]) without materializing it. Batched over blockIdx.z with strides.
// MODE 0: out = acc + bias[j]
// MODE 1: out = relu(acc + bias[j]) * bng[j]*rsqrt(1+eps) + bnb[j]
// Tile: 128x128x32, 256 threads (8 warps, 4x2), warp tile 32x64, mma m16n8k8.
template<int MODE>
__global__ __launch_bounds__(256) void gemm_nt(
    const float* __restrict__ A0, long sA0z, int K0,
    const float* __restrict__ A1, long sA1z, int lda1, int K1,
    const float* __restrict__ B,  long sBz,
    const float* __restrict__ bias, long sBiasZ,
    const float* __restrict__ bng, const float* __restrict__ bnb,
    float* __restrict__ C, long sCz, int N)
{
    const int K  = K0 + K1;
    const int KT = K >> 5;            // K is always a multiple of 32 here

    extern __shared__ float sm[];
    float* As  = sm;                  // 2 bufs * 128 rows * 36 (pad) floats
    float* Bsm = sm + 2 * 128 * 36;

    const int tid = threadIdx.x;
    const int z   = blockIdx.z;
    A0   += z * sA0z;
    if (A1) A1 += z * sA1z;
    B    += z * sBz;
    bias += z * sBiasZ;
    C    += z * sCz;

    const int bm = blockIdx.y * 128;
    const int bn = blockIdx.x * 128;

    const uint32_t sA = (uint32_t)__cvta_generic_to_shared(As);
    const uint32_t sB = (uint32_t)__cvta_generic_to_shared(Bsm);

    auto load_tile = [&](int kt, int buf) {
        const int kb = kt * 32;
#pragma unroll
        for (int i = 0; i < 4; i++) {
            int f   = tid + i * 256;
            int row = f >> 3;
            int c4  = (f & 7) * 4;
            int gk  = kb + c4;
            const float* src;
            if (gk < K0) src = A0 + (long)(bm + row) * K0   + gk;
            else         src = A1 + (long)(bm + row) * lda1 + (gk - K0);
            cp16(sA + (uint32_t)(((buf * 128 + row) * 36 + c4) * 4), src, 16);
        }
#pragma unroll
        for (int i = 0; i < 4; i++) {
            int f   = tid + i * 256;
            int row = f >> 3;
            int c4  = (f & 7) * 4;
            int gk  = kb + c4;
            bool ok = (bn + row) < N;
            const float* src = ok ? (B + (long)(bn + row) * K + gk) : B;
            cp16(sB + (uint32_t)(((buf * 128 + row) * 36 + c4) * 4), src, ok ? 16 : 0);
        }
    };

    float c[2][8][4];
#pragma unroll
    for (int a = 0; a < 2; a++)
#pragma unroll
        for (int b2 = 0; b2 < 8; b2++)
#pragma unroll
            for (int d = 0; d < 4; d++) c[a][b2][d] = 0.f;

    const int warp = tid >> 5, lane = tid & 31;
    const int wm = warp & 3, wn = warp >> 2;
    const int lr = lane >> 2, lc = lane & 3;

    load_tile(0, 0);
    asm volatile("cp.async.commit_group;\n");
    asm volatile("cp.async.wait_group 0;\n");
    __syncthreads();

    for (int kt = 0; kt < KT; kt++) {
        if (kt + 1 < KT) {
            load_tile(kt + 1, (kt + 1) & 1);
            asm volatile("cp.async.commit_group;\n");
        }
        const float* Ab = As  + (kt & 1) * 128 * 36;
        const float* Bb = Bsm + (kt & 1) * 128 * 36;
#pragma unroll
        for (int ks = 0; ks < 4; ks++) {
            const int k = ks * 8;
            uint32_t af[2][4];
#pragma unroll
            for (int mi = 0; mi < 2; mi++) {
                int r = wm * 32 + mi * 16 + lr;
                af[mi][0] = f2tf32(Ab[r * 36 + k + lc]);
                af[mi][1] = f2tf32(Ab[(r + 8) * 36 + k + lc]);
                af[mi][2] = f2tf32(Ab[r * 36 + k + lc + 4]);
                af[mi][3] = f2tf32(Ab[(r + 8) * 36 + k + lc + 4]);
            }
            uint32_t bf[8][2];
#pragma unroll
            for (int ni = 0; ni < 8; ni++) {
                int n = wn * 64 + ni * 8 + lr;
                bf[ni][0] = f2tf32(Bb[n * 36 + k + lc]);
                bf[ni][1] = f2tf32(Bb[n * 36 + k + lc + 4]);
            }
#pragma unroll
            for (int mi = 0; mi < 2; mi++)
#pragma unroll
                for (int ni = 0; ni < 8; ni++)
                    asm volatile(
                        "mma.sync.aligned.m16n8k8.row.col.f32.tf32.tf32.f32 "
                        "{%0,%1,%2,%3},{%4,%5,%6,%7},{%8,%9},{%0,%1,%2,%3};\n"
                        : "+f"(c[mi][ni][0]), "+f"(c[mi][ni][1]),
                          "+f"(c[mi][ni][2]), "+f"(c[mi][ni][3])
                        : "r"(af[mi][0]), "r"(af[mi][1]), "r"(af[mi][2]), "r"(af[mi][3]),
                          "r"(bf[ni][0]), "r"(bf[ni][1]));
        }
        if (kt + 1 < KT) asm volatile("cp.async.wait_group 0;\n");
        __syncthreads();
    }

    const float inv = rsqrtf(1.0f + 1e-5f);
#pragma unroll
    for (int mi = 0; mi < 2; mi++) {
        const int row = bm + wm * 32 + mi * 16 + lr;
#pragma unroll
        for (int ni = 0; ni < 8; ni++) {
            const int col = bn + wn * 64 + ni * 8 + 2 * lc;
#pragma unroll
            for (int h = 0; h < 2; h++) {
                const int r = row + h * 8;
#pragma unroll
                for (int q = 0; q < 2; q++) {
                    const int j = col + q;
                    if (j < N) {
                        float v = c[mi][ni][h * 2 + q] + bias[j];
                        if (MODE == 1) v = fmaxf(v, 0.f) * bng[j] * inv + bnb[j];
                        C[(long)r * N + j] = v;
                    }
                }
            }
        }
    }
}

// ---------------- fea_u = sum over the 19 branches of x ----------------
__global__ void reduce_x(const float* __restrict__ x, float* __restrict__ out) {
    long idx = (long)blockIdx.x * blockDim.x + threadIdx.x;
    if (idx >= (long)BSZ * DIMF) return;
    int b = (int)(idx / DIMF);
    int d = (int)(idx % DIMF);
    const float* p = x + (long)b * XROW + d;
    float s = 0.f;
#pragma unroll
    for (int m = 0; m < NBR; m++) s += p[m * DIMF];
    out[idx] = s;
}

// ---------------- softmax over m (19) + weighted sum with x ----------------
__global__ void softmax_wsum(const float* __restrict__ att,
                             const float* __restrict__ x,
                             float* __restrict__ out) {
    long idx = (long)blockIdx.x * blockDim.x + threadIdx.x;
    if (idx >= (long)BSZ * DIMF) return;
    int b = (int)(idx / DIMF);
    int o = (int)(idx % DIMF);
    float v[NBR];
    float mx = -1e30f;
#pragma unroll
    for (int m = 0; m < NBR; m++) {
        v[m] = att[((long)m * BSZ + b) * DIMF + o];
        mx = fmaxf(mx, v[m]);
    }
    float s = 0.f;
#pragma unroll
    for (int m = 0; m < NBR; m++) { v[m] = expf(v[m] - mx); s += v[m]; }
    const float invs = 1.f / s;
    float acc = 0.f;
    const float* xp = x + (long)b * XROW + o;
#pragma unroll
    for (int m = 0; m < NBR; m++) acc += v[m] * invs * xp[m * DIMF];
    out[idx] = acc;
}

// ---------------- launch ----------------
extern "C" void kernel_launch(void* const* d_in, const int* in_sizes, int n_in,
                              void* d_out, int out_size) {
    const float* x      = (const float*)d_in[0];
    const float* g      = (const float*)d_in[1];
    const float* fc1_W  = (const float*)d_in[2];
    const float* fc1_b  = (const float*)d_in[3];
    const float* bn1_g  = (const float*)d_in[4];
    const float* bn1_b  = (const float*)d_in[5];
    const float* fc2_W  = (const float*)d_in[6];
    const float* fc2_b  = (const float*)d_in[7];
    const float* fcs_W  = (const float*)d_in[8];
    const float* fcs_b  = (const float*)d_in[9];
    const float* gfcs_W = (const float*)d_in[10];
    const float* gfcs_b = (const float*)d_in[11];
    const float* l1_W   = (const float*)d_in[12];
    const float* l1_b   = (const float*)d_in[13];
    const float* bna_g  = (const float*)d_in[14];
    const float* bna_b  = (const float*)d_in[15];
    const float* l2_W   = (const float*)d_in[16];
    const float* l2_b   = (const float*)d_in[17];
    const float* bnb_g  = (const float*)d_in[18];
    const float* bnb_b  = (const float*)d_in[19];
    const float* l3_W   = (const float*)d_in[20];
    const float* l3_b   = (const float*)d_in[21];
    float* out = (float*)d_out;

    float *fea_u, *h1, *fea_z, *vec, *att, *fea_v, *hA, *hB;
    cudaGetSymbolAddress((void**)&fea_u, g_fea_u);
    cudaGetSymbolAddress((void**)&h1,    g_h1);
    cudaGetSymbolAddress((void**)&fea_z, g_fea_z);
    cudaGetSymbolAddress((void**)&vec,   g_vec);
    cudaGetSymbolAddress((void**)&att,   g_att);
    cudaGetSymbolAddress((void**)&fea_v, g_fea_v);
    cudaGetSymbolAddress((void**)&hA,    g_hA);
    cudaGetSymbolAddress((void**)&hB,    g_hB);

    const int SMEM = 2 * 2 * 128 * 36 * 4;  // 73728 bytes
    cudaFuncSetAttribute(gemm_nt<0>, cudaFuncAttributeMaxDynamicSharedMemorySize, SMEM);
    cudaFuncSetAttribute(gemm_nt<1>, cudaFuncAttributeMaxDynamicSharedMemorySize, SMEM);

    // 1) fea_u = sum_m x
    reduce_x<<<(BSZ * DIMF + 255) / 256, 256>>>(x, fea_u);

    // 2) h1 = BN(ReLU(fea_u @ fc1^T + b))
    gemm_nt<1><<<dim3(3, 32, 1), 256, SMEM>>>(
        fea_u, 0, DIMF, nullptr, 0, 0, 0,
        fc1_W, 0, fc1_b, 0, bn1_g, bn1_b, h1, 0, DD);

    // 3) fea_z = h1 @ fc2^T + b
    gemm_nt<0><<<dim3(3, 32, 1), 256, SMEM>>>(
        h1, 0, DD, nullptr, 0, 0, 0,
        fc2_W, 0, fc2_b, 0, nullptr, nullptr, fea_z, 0, DD);

    // 4) vec[m] = fea_z @ fcs_W[m]^T + fcs_b[m]   (batched, z = m)
    gemm_nt<0><<<dim3(3, 32, NBR), 256, SMEM>>>(
        fea_z, 0, DD, nullptr, 0, 0, 0,
        fcs_W, (long)DD * DD, fcs_b, DD, nullptr, nullptr,
        vec, (long)BSZ * DD, DD);

    // 5) att[m] = concat(vec[m], g[:,m,:]) @ gfcs_W[m]^T + gfcs_b[m]  (fused concat)
    gemm_nt<0><<<dim3(6, 32, NBR), 256, SMEM>>>(
        vec, (long)BSZ * DD, DD,
        g, (long)DIMF, XROW, DIMF,
        gfcs_W, (long)DIMF * (DIMF + DD), gfcs_b, DIMF, nullptr, nullptr,
        att, (long)BSZ * DIMF, DIMF);

    // 6) softmax over m + weighted sum with x
    softmax_wsum<<<(BSZ * DIMF + 255) / 256, 256>>>(att, x, fea_v);

    // 7) classifier head
    gemm_nt<1><<<dim3(1, 32, 1), 256, SMEM>>>(
        fea_v, 0, DIMF, nullptr, 0, 0, 0,
        l1_W, 0, l1_b, 0, bna_g, bna_b, hA, 0, 128);

    gemm_nt<1><<<dim3(1, 32, 1), 256, SMEM>>>(
        hA, 0, 128, nullptr, 0, 0, 0,
        l2_W, 0, l2_b, 0, bnb_g, bnb_b, hB, 0, 32);

    gemm_nt<0><<<dim3(1, 32, 1), 256, SMEM>>>(
        hB, 0, 32, nullptr, 0, 0, 0,
        l3_W, 0, l3_b, 0, nullptr, nullptr, out, 0, 20);
}

// round 3
// speedup vs baseline: 1.0397x; 1.0397x over previous
#include <cuda_runtime.h>
#include <cstdint>

#define NBR   19
#define DIMF  768
#define DD    384
#define BSZ   4096
#define XROW  (NBR * DIMF)   // 14592
#define GW    (DIMF + DD)    // 1152

// ---------------- scratch (device globals; no allocation allowed) ----------------
__device__ float g_fea_u[(size_t)BSZ * DIMF];
__device__ float g_h1[(size_t)BSZ * DD];
__device__ float g_fea_z[(size_t)BSZ * DD];
__device__ float g_att[(size_t)NBR * BSZ * DIMF];
__device__ float g_fea_v[(size_t)BSZ * DIMF];
__device__ float g_hA[(size_t)BSZ * 128];
__device__ float g_hB[(size_t)BSZ * 32];
__device__ float g_Wc[(size_t)NBR * DIMF * DD];    // folded weights gfcsA @ fcs_W
__device__ float g_fcsT[(size_t)NBR * DD * DD];    // fcs_W transposed
__device__ float g_bc[(size_t)NBR * DIMF];         // folded bias

// ---------------- helpers ----------------
__device__ __forceinline__ uint32_t f2tf32(float x) {
    uint32_t u;
    asm("cvt.rna.tf32.f32 %0, %1;" : "=r"(u) : "f"(x));
    return u;
}

// ---------------- generic tf32 NT GEMM: C[i][j] = sum_k A[i][k] * B[j][k] ----------------
// A and B each split into two K-segments (segment 0: K0 cols, segment 1: K1 cols),
// with independent base/lda/batch-stride, to fuse concat without materializing.
// Data is rounded to tf32 ONCE while staging into smem; the MMA loop feeds smem
// floats directly (reinterpret) with zero per-fragment conversions.
// MODE 0: out = acc (+ bias[j] if bias)
// MODE 1: out = relu(acc + bias[j]) * bng[j]*rsqrt(1+eps) + bnb[j]
// Tile 128x128x32, 256 threads (8 warps 4x2), warp tile 32x64, mma m16n8k8.
template<int MODE>
__global__ __launch_bounds__(256, 2) void gemm2(
    const float* __restrict__ A0, long sA0z, int lda0, int K0,
    const float* __restrict__ A1, long sA1z, int lda1, int K1,
    const float* __restrict__ B0, long sB0z, int ldb0,
    const float* __restrict__ B1, long sB1z, int ldb1,
    const float* __restrict__ bias, long sBiasZ,
    const float* __restrict__ bng, const float* __restrict__ bnb,
    float* __restrict__ C, long sCz, int N)
{
    const int K  = K0 + K1;
    const int KT = K >> 5;   // K always a multiple of 32

    extern __shared__ float sm[];
    float* As  = sm;                  // [2][128][36]
    float* Bsm = sm + 2 * 128 * 36;   // [2][128][36]

    const int tid = threadIdx.x;
    const int z   = blockIdx.z;
    A0 += z * sA0z;
    if (A1) A1 += z * sA1z;
    B0 += z * sB0z;
    if (B1) B1 += z * sB1z;
    if (bias) bias += z * sBiasZ;
    C  += z * sCz;

    const int bm = blockIdx.y * 128;
    const int bn = blockIdx.x * 128;

    const int lrow = tid >> 3;        // 0..31
    const int c4   = (tid & 7) * 4;   // 0,4,..,28

    float4 a_stg[4], b_stg[4];

    auto ldTiles = [&](int kt) {
        const int gk = kt * 32 + c4;
#pragma unroll
        for (int i = 0; i < 4; i++) {
            const int row = lrow + i * 32;
            const float* s = (gk < K0) ? (A0 + (long)(bm + row) * lda0 + gk)
                                       : (A1 + (long)(bm + row) * lda1 + (gk - K0));
            a_stg[i] = *(const float4*)s;
        }
#pragma unroll
        for (int i = 0; i < 4; i++) {
            const int row = lrow + i * 32;
            int j = bn + row; if (j > N - 1) j = N - 1;
            const float* s = (gk < K0) ? (B0 + (long)j * ldb0 + gk)
                                       : (B1 + (long)j * ldb1 + (gk - K0));
            b_stg[i] = *(const float4*)s;
        }
    };
    auto stTiles = [&](int buf) {
        float* a = As  + buf * 128 * 36;
        float* b = Bsm + buf * 128 * 36;
#pragma unroll
        for (int i = 0; i < 4; i++) {
            const int row = lrow + i * 32;
            float4 t;
            t.x = __uint_as_float(f2tf32(a_stg[i].x));
            t.y = __uint_as_float(f2tf32(a_stg[i].y));
            t.z = __uint_as_float(f2tf32(a_stg[i].z));
            t.w = __uint_as_float(f2tf32(a_stg[i].w));
            *(float4*)(a + row * 36 + c4) = t;
        }
#pragma unroll
        for (int i = 0; i < 4; i++) {
            const int row = lrow + i * 32;
            float4 t;
            t.x = __uint_as_float(f2tf32(b_stg[i].x));
            t.y = __uint_as_float(f2tf32(b_stg[i].y));
            t.z = __uint_as_float(f2tf32(b_stg[i].z));
            t.w = __uint_as_float(f2tf32(b_stg[i].w));
            *(float4*)(b + row * 36 + c4) = t;
        }
    };

    float c[2][8][4];
#pragma unroll
    for (int a = 0; a < 2; a++)
#pragma unroll
        for (int b2 = 0; b2 < 8; b2++)
#pragma unroll
            for (int d = 0; d < 4; d++) c[a][b2][d] = 0.f;

    const int warp = tid >> 5, lane = tid & 31;
    const int wm = warp & 3, wn = warp >> 2;
    const int lr = lane >> 2, lc = lane & 3;

    // prologue: stage tile 0
    ldTiles(0);
    stTiles(0);
    __syncthreads();

    for (int kt = 0; kt < KT; kt++) {
        const bool has_next = (kt + 1 < KT);
        if (has_next) ldTiles(kt + 1);   // LDGs issued before the MMA block

        const float* Ab = As  + (kt & 1) * 128 * 36;
        const float* Bb = Bsm + (kt & 1) * 128 * 36;
#pragma unroll
        for (int ks = 0; ks < 4; ks++) {
            const int k = ks * 8;
            uint32_t af[2][4];
#pragma unroll
            for (int mi = 0; mi < 2; mi++) {
                const int r = wm * 32 + mi * 16 + lr;
                af[mi][0] = __float_as_uint(Ab[r * 36 + k + lc]);
                af[mi][1] = __float_as_uint(Ab[(r + 8) * 36 + k + lc]);
                af[mi][2] = __float_as_uint(Ab[r * 36 + k + lc + 4]);
                af[mi][3] = __float_as_uint(Ab[(r + 8) * 36 + k + lc + 4]);
            }
#pragma unroll
            for (int ni = 0; ni < 8; ni++) {
                const int n = wn * 64 + ni * 8 + lr;
                uint32_t b0 = __float_as_uint(Bb[n * 36 + k + lc]);
                uint32_t b1 = __float_as_uint(Bb[n * 36 + k + lc + 4]);
#pragma unroll
                for (int mi = 0; mi < 2; mi++)
                    asm volatile(
                        "mma.sync.aligned.m16n8k8.row.col.f32.tf32.tf32.f32 "
                        "{%0,%1,%2,%3},{%4,%5,%6,%7},{%8,%9},{%0,%1,%2,%3};\n"
                        : "+f"(c[mi][ni][0]), "+f"(c[mi][ni][1]),
                          "+f"(c[mi][ni][2]), "+f"(c[mi][ni][3])
                        : "r"(af[mi][0]), "r"(af[mi][1]), "r"(af[mi][2]), "r"(af[mi][3]),
                          "r"(b0), "r"(b1));
            }
        }
        if (has_next) stTiles((kt + 1) & 1);
        __syncthreads();
    }

    const float inv = rsqrtf(1.0f + 1e-5f);
#pragma unroll
    for (int mi = 0; mi < 2; mi++) {
        const int row = bm + wm * 32 + mi * 16 + lr;
#pragma unroll
        for (int ni = 0; ni < 8; ni++) {
            const int col = bn + wn * 64 + ni * 8 + 2 * lc;
#pragma unroll
            for (int h = 0; h < 2; h++) {
                const int r = row + h * 8;
#pragma unroll
                for (int q = 0; q < 2; q++) {
                    const int j = col + q;
                    if (j < N) {
                        float v = c[mi][ni][h * 2 + q];
                        if (bias) v += bias[j];
                        if (MODE == 1) v = fmaxf(v, 0.f) * bng[j] * inv + bnb[j];
                        C[(long)r * N + j] = v;
                    }
                }
            }
        }
    }
}

// ---------------- fea_u = sum over the 19 branches of x ----------------
__global__ void reduce_x(const float* __restrict__ x, float* __restrict__ out) {
    long idx = (long)blockIdx.x * blockDim.x + threadIdx.x;
    if (idx >= (long)BSZ * DIMF) return;
    int b = (int)(idx / DIMF);
    int d = (int)(idx % DIMF);
    const float* p = x + (long)b * XROW + d;
    float s = 0.f;
#pragma unroll
    for (int m = 0; m < NBR; m++) s += p[m * DIMF];
    out[idx] = s;
}

// ---------------- transpose fcs_W: T[m][d][i] = W[m][i][d] ----------------
__global__ void transpose_fcs(const float* __restrict__ W, float* __restrict__ T) {
    __shared__ float t[32][33];
    const int m  = blockIdx.z;
    const int i0 = blockIdx.y * 32, d0 = blockIdx.x * 32;
    const float* src = W + (long)m * DD * DD;
    float* dst       = T + (long)m * DD * DD;
    const int x = threadIdx.x, y = threadIdx.y;   // block (32,8)
#pragma unroll
    for (int yy = y; yy < 32; yy += 8)
        t[yy][x] = src[(long)(i0 + yy) * DD + d0 + x];
    __syncthreads();
#pragma unroll
    for (int yy = y; yy < 32; yy += 8)
        dst[(long)(d0 + yy) * DD + i0 + x] = t[x][yy];
}

// ---------------- folded bias: bc[m][o] = gfcs_b[m][o] + gfcsA[m][o,:] . fcs_b[m] ----------------
__global__ void fold_bias(const float* __restrict__ gfcsW, const float* __restrict__ gfcsB,
                          const float* __restrict__ fcsB, float* __restrict__ bc) {
    int idx = blockIdx.x * blockDim.x + threadIdx.x;
    if (idx >= NBR * DIMF) return;
    int m = idx / DIMF, o = idx % DIMF;
    const float* w  = gfcsW + ((long)m * DIMF + o) * GW;
    const float* fb = fcsB + m * DD;
    float s = gfcsB[idx];
    for (int i = 0; i < DD; i++) s += w[i] * fb[i];
    bc[idx] = s;
}

// ---------------- softmax over m (19) + weighted sum with x ----------------
__global__ void softmax_wsum(const float* __restrict__ att,
                             const float* __restrict__ x,
                             float* __restrict__ out) {
    long idx = (long)blockIdx.x * blockDim.x + threadIdx.x;
    if (idx >= (long)BSZ * DIMF) return;
    int b = (int)(idx / DIMF);
    int o = (int)(idx % DIMF);
    float v[NBR];
    float mx = -1e30f;
#pragma unroll
    for (int m = 0; m < NBR; m++) {
        v[m] = att[((long)m * BSZ + b) * DIMF + o];
        mx = fmaxf(mx, v[m]);
    }
    float s = 0.f;
#pragma unroll
    for (int m = 0; m < NBR; m++) { v[m] = expf(v[m] - mx); s += v[m]; }
    const float invs = 1.f / s;
    float acc = 0.f;
    const float* xp = x + (long)b * XROW + o;
#pragma unroll
    for (int m = 0; m < NBR; m++) acc += v[m] * invs * xp[m * DIMF];
    out[idx] = acc;
}

// ---------------- launch ----------------
extern "C" void kernel_launch(void* const* d_in, const int* in_sizes, int n_in,
                              void* d_out, int out_size) {
    const float* x      = (const float*)d_in[0];
    const float* g      = (const float*)d_in[1];
    const float* fc1_W  = (const float*)d_in[2];
    const float* fc1_b  = (const float*)d_in[3];
    const float* bn1_g  = (const float*)d_in[4];
    const float* bn1_b  = (const float*)d_in[5];
    const float* fc2_W  = (const float*)d_in[6];
    const float* fc2_b  = (const float*)d_in[7];
    const float* fcs_W  = (const float*)d_in[8];
    const float* fcs_b  = (const float*)d_in[9];
    const float* gfcs_W = (const float*)d_in[10];
    const float* gfcs_b = (const float*)d_in[11];
    const float* l1_W   = (const float*)d_in[12];
    const float* l1_b   = (const float*)d_in[13];
    const float* bna_g  = (const float*)d_in[14];
    const float* bna_b  = (const float*)d_in[15];
    const float* l2_W   = (const float*)d_in[16];
    const float* l2_b   = (const float*)d_in[17];
    const float* bnb_g  = (const float*)d_in[18];
    const float* bnb_b  = (const float*)d_in[19];
    const float* l3_W   = (const float*)d_in[20];
    const float* l3_b   = (const float*)d_in[21];
    float* out = (float*)d_out;

    float *fea_u, *h1, *fea_z, *att, *fea_v, *hA, *hB, *Wc, *fcsT, *bc;
    cudaGetSymbolAddress((void**)&fea_u, g_fea_u);
    cudaGetSymbolAddress((void**)&h1,    g_h1);
    cudaGetSymbolAddress((void**)&fea_z, g_fea_z);
    cudaGetSymbolAddress((void**)&att,   g_att);
    cudaGetSymbolAddress((void**)&fea_v, g_fea_v);
    cudaGetSymbolAddress((void**)&hA,    g_hA);
    cudaGetSymbolAddress((void**)&hB,    g_hB);
    cudaGetSymbolAddress((void**)&Wc,    g_Wc);
    cudaGetSymbolAddress((void**)&fcsT,  g_fcsT);
    cudaGetSymbolAddress((void**)&bc,    g_bc);

    const int SMEM = 2 * 2 * 128 * 36 * 4;  // 73728 bytes
    cudaFuncSetAttribute(gemm2<0>, cudaFuncAttributeMaxDynamicSharedMemorySize, SMEM);
    cudaFuncSetAttribute(gemm2<1>, cudaFuncAttributeMaxDynamicSharedMemorySize, SMEM);

    // setup: transpose fcs, fold bias (independent of batch path)
    transpose_fcs<<<dim3(12, 12, NBR), dim3(32, 8)>>>(fcs_W, fcsT);
    fold_bias<<<(NBR * DIMF + 255) / 256, 256>>>(gfcs_W, gfcs_b, fcs_b, bc);

    // Wc[m] = gfcsA[m] @ fcs_W[m]  => C[o][d] = sum_i gfcsA[o][i] * fcsT[d][i]
    gemm2<0><<<dim3(3, 6, NBR), 256, SMEM>>>(
        gfcs_W, (long)DIMF * GW, GW, DD,  nullptr, 0, 0, 0,
        fcsT, (long)DD * DD, DD,  nullptr, 0, 0,
        nullptr, 0, nullptr, nullptr,
        Wc, (long)DIMF * DD, DD);

    // 1) fea_u = sum_m x
    reduce_x<<<(BSZ * DIMF + 255) / 256, 256>>>(x, fea_u);

    // 2) h1 = BN(ReLU(fea_u @ fc1^T + b))
    gemm2<1><<<dim3(3, 32, 1), 256, SMEM>>>(
        fea_u, 0, DIMF, DIMF,  nullptr, 0, 0, 0,
        fc1_W, 0, DIMF,  nullptr, 0, 0,
        fc1_b, 0, bn1_g, bn1_b, h1, 0, DD);

    // 3) fea_z = h1 @ fc2^T + b
    gemm2<0><<<dim3(3, 32, 1), 256, SMEM>>>(
        h1, 0, DD, DD,  nullptr, 0, 0, 0,
        fc2_W, 0, DD,  nullptr, 0, 0,
        fc2_b, 0, nullptr, nullptr, fea_z, 0, DD);

    // 4) att[m] = fea_z @ Wc[m]^T + g[:,m,:] @ gfcsB[m]^T + bc[m]
    gemm2<0><<<dim3(6, 32, NBR), 256, SMEM>>>(
        fea_z, 0, DD, DD,
        g, (long)DIMF, XROW, DIMF,
        Wc, (long)DIMF * DD, DD,
        gfcs_W + DD, (long)DIMF * GW, GW,
        bc, DIMF, nullptr, nullptr,
        att, (long)BSZ * DIMF, DIMF);

    // 5) softmax over m + weighted sum with x
    softmax_wsum<<<(BSZ * DIMF + 255) / 256, 256>>>(att, x, fea_v);

    // 6) classifier head
    gemm2<1><<<dim3(1, 32, 1), 256, SMEM>>>(
        fea_v, 0, DIMF, DIMF,  nullptr, 0, 0, 0,
        l1_W, 0, DIMF,  nullptr, 0, 0,
        l1_b, 0, bna_g, bna_b, hA, 0, 128);

    gemm2<1><<<dim3(1, 32, 1), 256, SMEM>>>(
        hA, 0, 128, 128,  nullptr, 0, 0, 0,
        l2_W, 0, 128,  nullptr, 0, 0,
        l2_b, 0, bnb_g, bnb_b, hB, 0, 32);

    gemm2<0><<<dim3(1, 32, 1), 256, SMEM>>>(
        hB, 0, 32, 32,  nullptr, 0, 0, 0,
        l3_W, 0, 32,  nullptr, 0, 0,
        l3_b, 0, nullptr, nullptr, out, 0, 20);
}

// round 6
// speedup vs baseline: 1.1853x; 1.1401x over previous
#include <cuda_runtime.h>
#include <cstdint>

#define NBR   19
#define DIMF  768
#define DD    384
#define BSZ   4096
#define XROW  (NBR * DIMF)   // 14592
#define GW    (DIMF + DD)    // 1152

// ---------------- scratch (device globals) ----------------
__device__ float g_fea_u[(size_t)BSZ * DIMF];
__device__ float g_h1[(size_t)BSZ * DD];
__device__ float g_fea_z[(size_t)BSZ * DD];
__device__ float g_att[(size_t)NBR * BSZ * DIMF];
__device__ float g_fea_v[(size_t)BSZ * DIMF];
__device__ float g_hA[(size_t)BSZ * 128];
__device__ float g_hB[(size_t)BSZ * 32];
__device__ float g_Wc[(size_t)NBR * DIMF * DD];
__device__ float g_fcsT[(size_t)NBR * DD * DD];
__device__ float g_bc[(size_t)NBR * DIMF];

// ---------------- helpers ----------------
__device__ __forceinline__ uint32_t f2tf32(float x) {
    uint32_t u;
    asm("cvt.rna.tf32.f32 %0, %1;" : "=r"(u) : "f"(x));
    return u;
}
__device__ __forceinline__ float4 rnd4(float4 v) {
    v.x = __uint_as_float(f2tf32(v.x));
    v.y = __uint_as_float(f2tf32(v.y));
    v.z = __uint_as_float(f2tf32(v.z));
    v.w = __uint_as_float(f2tf32(v.w));
    return v;
}
__device__ __forceinline__ void ldsm4(uint32_t a, uint32_t r[4]) {
    asm volatile("ldmatrix.sync.aligned.m8n8.x4.shared.b16 {%0,%1,%2,%3}, [%4];"
                 : "=r"(r[0]), "=r"(r[1]), "=r"(r[2]), "=r"(r[3]) : "r"(a));
}

// ---------------- generic tf32 NT GEMM: C[i][j] = sum_k A[i][k] * B[j][k] ----------------
// A and B each split into two K-segments to fuse concat/fold without materializing.
// Data rounded to tf32 once while staging into smem; fragments loaded via ldmatrix
// (non-trans b16 ldmatrix == 32-bit gather matching the tf32 m16n8k8 fragment layout).
// MODE 0: out = acc (+ bias[j] if bias)
// MODE 1: out = relu(acc + bias[j]) * bng[j]*rsqrt(1+eps) + bnb[j]
// Tile 128x128x32, 256 threads (8 warps 4x2), warp tile 32x64, mma m16n8k8.
template<int MODE>
__global__ __launch_bounds__(256, 2) void gemm2(
    const float* __restrict__ A0, long sA0z, int lda0, int K0,
    const float* __restrict__ A1, long sA1z, int lda1, int K1,
    const float* __restrict__ B0, long sB0z, int ldb0,
    const float* __restrict__ B1, long sB1z, int ldb1,
    const float* __restrict__ bias, long sBiasZ,
    const float* __restrict__ bng, const float* __restrict__ bnb,
    float* __restrict__ C, long sCz, int N)
{
    const int K  = K0 + K1;
    const int KT = K >> 5;

    extern __shared__ float sm[];
    float* As  = sm;                  // [2][128][36]
    float* Bsm = sm + 2 * 128 * 36;   // [2][128][36]

    const int tid = threadIdx.x;
    const int z   = blockIdx.z;
    A0 += z * sA0z;
    if (A1) A1 += z * sA1z;
    B0 += z * sB0z;
    if (B1) B1 += z * sB1z;
    if (bias) bias += z * sBiasZ;
    C  += z * sCz;

    const int bm = blockIdx.y * 128;
    const int bn = blockIdx.x * 128;

    const int lrow = tid >> 3;
    const int c4   = (tid & 7) * 4;

    float4 a_stg[4], b_stg[4];

    auto ldTiles = [&](int kt) {
        const int gk = kt * 32 + c4;
#pragma unroll
        for (int i = 0; i < 4; i++) {
            const int row = lrow + i * 32;
            const float* s = (gk < K0) ? (A0 + (long)(bm + row) * lda0 + gk)
                                       : (A1 + (long)(bm + row) * lda1 + (gk - K0));
            a_stg[i] = *(const float4*)s;
        }
#pragma unroll
        for (int i = 0; i < 4; i++) {
            const int row = lrow + i * 32;
            int j = bn + row; if (j > N - 1) j = N - 1;
            const float* s = (gk < K0) ? (B0 + (long)j * ldb0 + gk)
                                       : (B1 + (long)j * ldb1 + (gk - K0));
            b_stg[i] = *(const float4*)s;
        }
    };
    auto stTiles = [&](int buf) {
        float* a = As  + buf * 128 * 36;
        float* b = Bsm + buf * 128 * 36;
#pragma unroll
        for (int i = 0; i < 4; i++)
            *(float4*)(a + (lrow + i * 32) * 36 + c4) = rnd4(a_stg[i]);
#pragma unroll
        for (int i = 0; i < 4; i++)
            *(float4*)(b + (lrow + i * 32) * 36 + c4) = rnd4(b_stg[i]);
    };

    float c[2][8][4];
#pragma unroll
    for (int a = 0; a < 2; a++)
#pragma unroll
        for (int b2 = 0; b2 < 8; b2++)
#pragma unroll
            for (int d = 0; d < 4; d++) c[a][b2][d] = 0.f;

    const int warp = tid >> 5, lane = tid & 31;
    const int wm = warp & 3, wn = warp >> 2;
    const int lr = lane >> 2, lc = lane & 3;

    // ldmatrix per-lane address offsets (bytes, within a buffer)
    // A: matrix j of x4 = {rows +0(j bit0 ? +8), cols k + (j>>1? wait see below)}
    //   layout chosen: m0 rows r..r+7 @k, m1 rows r+8..r+15 @k, m2 rows r..r+7 @k+4, m3 rows r+8..+15 @k+4
    //   lane supplies addr for matrix (lane>>3), row (lane&7)
    const int a_row = wm * 32 + ((lane >> 3) & 1) * 8 + (lane & 7);
    const int a_col = (lane >> 4) * 4;
    const uint32_t aoff = (uint32_t)((a_row * 36 + a_col) * 4);
    // B: m0 = rows ni..+7 @k, m1 = rows ni..+7 @k+4, m2 = rows ni+8..+15 @k, m3 = rows ni+8..+15 @k+4
    const int b_row = wn * 64 + (lane >> 4) * 8 + (lane & 7);
    const int b_col = ((lane >> 3) & 1) * 4;
    const uint32_t boff = (uint32_t)((b_row * 36 + b_col) * 4);

    const uint32_t sA = (uint32_t)__cvta_generic_to_shared(As);
    const uint32_t sB = (uint32_t)__cvta_generic_to_shared(Bsm);
    const uint32_t BUF = 128 * 36 * 4;

    ldTiles(0);
    stTiles(0);
    __syncthreads();

    for (int kt = 0; kt < KT; kt++) {
        const bool has_next = (kt + 1 < KT);
        if (has_next) ldTiles(kt + 1);

        const uint32_t aBuf = sA + (kt & 1) * BUF + aoff;
        const uint32_t bBuf = sB + (kt & 1) * BUF + boff;
#pragma unroll
        for (int ks = 0; ks < 4; ks++) {
            const uint32_t kByte = (uint32_t)(ks * 8 * 4);
            uint32_t af[2][4];
#pragma unroll
            for (int mi = 0; mi < 2; mi++)
                ldsm4(aBuf + mi * (16 * 36 * 4) + kByte, af[mi]);
            uint32_t bf[4][4];
#pragma unroll
            for (int np = 0; np < 4; np++)
                ldsm4(bBuf + np * (16 * 36 * 4) + kByte, bf[np]);
#pragma unroll
            for (int np = 0; np < 4; np++)
#pragma unroll
                for (int s = 0; s < 2; s++) {
                    const int ni = np * 2 + s;
#pragma unroll
                    for (int mi = 0; mi < 2; mi++)
                        asm volatile(
                            "mma.sync.aligned.m16n8k8.row.col.f32.tf32.tf32.f32 "
                            "{%0,%1,%2,%3},{%4,%5,%6,%7},{%8,%9},{%0,%1,%2,%3};\n"
                            : "+f"(c[mi][ni][0]), "+f"(c[mi][ni][1]),
                              "+f"(c[mi][ni][2]), "+f"(c[mi][ni][3])
                            : "r"(af[mi][0]), "r"(af[mi][1]),
                              "r"(af[mi][2]), "r"(af[mi][3]),
                              "r"(bf[np][2 * s]), "r"(bf[np][2 * s + 1]));
                }
        }
        if (has_next) stTiles((kt + 1) & 1);
        __syncthreads();
    }

    const float inv = rsqrtf(1.0f + 1e-5f);
#pragma unroll
    for (int mi = 0; mi < 2; mi++) {
        const int row = bm + wm * 32 + mi * 16 + lr;
#pragma unroll
        for (int ni = 0; ni < 8; ni++) {
            const int col = bn + wn * 64 + ni * 8 + 2 * lc;
#pragma unroll
            for (int h = 0; h < 2; h++) {
                const int r = row + h * 8;
#pragma unroll
                for (int q = 0; q < 2; q++) {
                    const int j = col + q;
                    if (j < N) {
                        float v = c[mi][ni][h * 2 + q];
                        if (bias) v += bias[j];
                        if (MODE == 1) v = fmaxf(v, 0.f) * bng[j] * inv + bnb[j];
                        C[(long)r * N + j] = v;
                    }
                }
            }
        }
    }
}

// ---------------- fea_u = sum over the 19 branches of x ----------------
__global__ void reduce_x(const float* __restrict__ x, float* __restrict__ out) {
    long idx = (long)blockIdx.x * blockDim.x + threadIdx.x;
    if (idx >= (long)BSZ * DIMF) return;
    int b = (int)(idx / DIMF);
    int d = (int)(idx % DIMF);
    const float* p = x + (long)b * XROW + d;
    float s = 0.f;
#pragma unroll
    for (int mm = 0; mm < NBR; mm++) s += p[mm * DIMF];
    out[idx] = s;
}

// ---------------- setup: transpose fcs_W  +  folded bias (merged) ----------------
__global__ void setup_misc(const float* __restrict__ fcsW, float* __restrict__ fcsT,
                           const float* __restrict__ gfcsW, const float* __restrict__ gfcsB,
                           const float* __restrict__ fcsB, float* __restrict__ bc)
{
    const int m = blockIdx.z;
    if (blockIdx.y < 12) {
        __shared__ float t[32][33];
        const int i0 = blockIdx.y * 32, d0 = blockIdx.x * 32;
        const float* src = fcsW + (size_t)m * DD * DD;
        float* dst       = fcsT + (size_t)m * DD * DD;
        const int x = threadIdx.x, y = threadIdx.y;
#pragma unroll
        for (int yy = y; yy < 32; yy += 8)
            t[yy][x] = src[(size_t)(i0 + yy) * DD + d0 + x];
        __syncthreads();
#pragma unroll
        for (int yy = y; yy < 32; yy += 8)
            dst[(size_t)(d0 + yy) * DD + i0 + x] = t[x][yy];
    } else {
        const int tid = threadIdx.y * 32 + threadIdx.x;
        const int w = tid >> 5, lane = tid & 31;
        const float* fb = fcsB + m * DD;
        for (int j = 0; j < 8; j++) {
            const int o = blockIdx.x * 64 + w * 8 + j;
            const float* wp = gfcsW + ((size_t)m * DIMF + o) * GW;
            float s = 0.f;
            for (int i = lane; i < DD; i += 32) s += wp[i] * fb[i];
#pragma unroll
            for (int off = 16; off; off >>= 1) s += __shfl_xor_sync(0xffffffffu, s, off);
            if (lane == 0) bc[(size_t)m * DIMF + o] = s + gfcsB[(size_t)m * DIMF + o];
        }
    }
}

// ---------------- softmax over m + weighted sum with x ----------------
__global__ void softmax_wsum(const float* __restrict__ att,
                             const float* __restrict__ x,
                             float* __restrict__ out) {
    long idx = (long)blockIdx.x * blockDim.x + threadIdx.x;
    if (idx >= (long)BSZ * DIMF) return;
    int b = (int)(idx / DIMF);
    int o = (int)(idx % DIMF);
    float v[NBR];
    float mx = -1e30f;
#pragma unroll
    for (int mm = 0; mm < NBR; mm++) {
        v[mm] = att[((long)mm * BSZ + b) * DIMF + o];
        mx = fmaxf(mx, v[mm]);
    }
    float s = 0.f;
#pragma unroll
    for (int mm = 0; mm < NBR; mm++) { v[mm] = expf(v[mm] - mx); s += v[mm]; }
    const float invs = 1.f / s;
    float acc = 0.f;
    const float* xp = x + (long)b * XROW + o;
#pragma unroll
    for (int mm = 0; mm < NBR; mm++) acc += v[mm] * invs * xp[mm * DIMF];
    out[idx] = acc;
}

// ---------------- launch ----------------
extern "C" void kernel_launch(void* const* d_in, const int* in_sizes, int n_in,
                              void* d_out, int out_size) {
    const float* x      = (const float*)d_in[0];
    const float* g      = (const float*)d_in[1];
    const float* fc1_W  = (const float*)d_in[2];
    const float* fc1_b  = (const float*)d_in[3];
    const float* bn1_g  = (const float*)d_in[4];
    const float* bn1_b  = (const float*)d_in[5];
    const float* fc2_W  = (const float*)d_in[6];
    const float* fc2_b  = (const float*)d_in[7];
    const float* fcs_W  = (const float*)d_in[8];
    const float* fcs_b  = (const float*)d_in[9];
    const float* gfcs_W = (const float*)d_in[10];
    const float* gfcs_b = (const float*)d_in[11];
    const float* l1_W   = (const float*)d_in[12];
    const float* l1_b   = (const float*)d_in[13];
    const float* bna_g  = (const float*)d_in[14];
    const float* bna_b  = (const float*)d_in[15];
    const float* l2_W   = (const float*)d_in[16];
    const float* l2_b   = (const float*)d_in[17];
    const float* bnb_g  = (const float*)d_in[18];
    const float* bnb_b  = (const float*)d_in[19];
    const float* l3_W   = (const float*)d_in[20];
    const float* l3_b   = (const float*)d_in[21];
    float* out = (float*)d_out;

    float *fea_u, *h1, *fea_z, *att, *fea_v, *hA, *hB, *Wc, *fcsT, *bc;
    cudaGetSymbolAddress((void**)&fea_u, g_fea_u);
    cudaGetSymbolAddress((void**)&h1,    g_h1);
    cudaGetSymbolAddress((void**)&fea_z, g_fea_z);
    cudaGetSymbolAddress((void**)&att,   g_att);
    cudaGetSymbolAddress((void**)&fea_v, g_fea_v);
    cudaGetSymbolAddress((void**)&hA,    g_hA);
    cudaGetSymbolAddress((void**)&hB,    g_hB);
    cudaGetSymbolAddress((void**)&Wc,    g_Wc);
    cudaGetSymbolAddress((void**)&fcsT,  g_fcsT);
    cudaGetSymbolAddress((void**)&bc,    g_bc);

    const int SMEM = 2 * 2 * 128 * 36 * 4;  // 73728 B
    cudaFuncSetAttribute(gemm2<0>, cudaFuncAttributeMaxDynamicSharedMemorySize, SMEM);
    cudaFuncSetAttribute(gemm2<1>, cudaFuncAttributeMaxDynamicSharedMemorySize, SMEM);

    // 1) transpose fcs + folded bias
    setup_misc<<<dim3(12, 13, NBR), dim3(32, 8)>>>(fcs_W, fcsT, gfcs_W, gfcs_b, fcs_b, bc);

    // 2) Wc[m] = gfcsA[m] @ fcs_W[m]
    gemm2<0><<<dim3(3, 6, NBR), 256, SMEM>>>(
        gfcs_W, (long)DIMF * GW, GW, DD,  nullptr, 0, 0, 0,
        fcsT, (long)DD * DD, DD,  nullptr, 0, 0,
        nullptr, 0, nullptr, nullptr,
        Wc, (long)DIMF * DD, DD);

    // 3) fea_u = sum_m x
    reduce_x<<<(BSZ * DIMF + 255) / 256, 256>>>(x, fea_u);

    // 4) h1 = BN(ReLU(fea_u @ fc1^T + b))
    gemm2<1><<<dim3(3, 32, 1), 256, SMEM>>>(
        fea_u, 0, DIMF, DIMF,  nullptr, 0, 0, 0,
        fc1_W, 0, DIMF,  nullptr, 0, 0,
        fc1_b, 0, bn1_g, bn1_b, h1, 0, DD);

    // 5) fea_z = h1 @ fc2^T + b
    gemm2<0><<<dim3(3, 32, 1), 256, SMEM>>>(
        h1, 0, DD, DD,  nullptr, 0, 0, 0,
        fc2_W, 0, DD,  nullptr, 0, 0,
        fc2_b, 0, nullptr, nullptr, fea_z, 0, DD);

    // 6) att[m] = fea_z @ Wc[m]^T + g[:,m,:] @ gfcsB[m]^T + bc[m]
    gemm2<0><<<dim3(6, 32, NBR), 256, SMEM>>>(
        fea_z, 0, DD, DD,
        g, (long)DIMF, XROW, DIMF,
        Wc, (long)DIMF * DD, DD,
        gfcs_W + DD, (long)DIMF * GW, GW,
        bc, DIMF, nullptr, nullptr,
        att, (long)BSZ * DIMF, DIMF);

    // 7) softmax over m + weighted sum with x
    softmax_wsum<<<(BSZ * DIMF + 255) / 256, 256>>>(att, x, fea_v);

    // 8-10) classifier head
    gemm2<1><<<dim3(1, 32, 1), 256, SMEM>>>(
        fea_v, 0, DIMF, DIMF,  nullptr, 0, 0, 0,
        l1_W, 0, DIMF,  nullptr, 0, 0,
        l1_b, 0, bna_g, bna_b, hA, 0, 128);

    gemm2<1><<<dim3(1, 32, 1), 256, SMEM>>>(
        hA, 0, 128, 128,  nullptr, 0, 0, 0,
        l2_W, 0, 128,  nullptr, 0, 0,
        l2_b, 0, bnb_g, bnb_b, hB, 0, 32);

    gemm2<0><<<dim3(1, 32, 1), 256, SMEM>>>(
        hB, 0, 32, 32,  nullptr, 0, 0, 0,
        l3_W, 0, 32,  nullptr, 0, 0,
        l3_b, 0, nullptr, nullptr, out, 0, 20);
}

// round 7
// speedup vs baseline: 1.3053x; 1.1013x over previous
#include <cuda_runtime.h>
#include <cstdint>

#define NBR   19
#define DIMF  768
#define DD    384
#define BSZ   4096
#define XROW  (NBR * DIMF)   // 14592
#define GW    (DIMF + DD)    // 1152

// ---------------- scratch (device globals) ----------------
__device__ float g_fea_u[(size_t)BSZ * DIMF];
__device__ float g_h1[(size_t)BSZ * DD];
__device__ float g_fea_z[(size_t)BSZ * DD];
__device__ float g_att[(size_t)NBR * BSZ * DIMF];
__device__ float g_fea_v[(size_t)BSZ * DIMF];
__device__ float g_hA[(size_t)BSZ * 128];
__device__ float g_hB[(size_t)BSZ * 32];
__device__ float g_Wc[(size_t)NBR * DIMF * DD];
__device__ float g_fcsT[(size_t)NBR * DD * DD];
__device__ float g_bc[(size_t)NBR * DIMF];
__device__ float g_gr[(size_t)BSZ * XROW];          // tf32-rounded g
__device__ float g_WB[(size_t)NBR * DIMF * DIMF];   // tf32-rounded gfcsB

// ---------------- helpers ----------------
__device__ __forceinline__ uint32_t f2tf32(float x) {
    uint32_t u;
    asm("cvt.rna.tf32.f32 %0, %1;" : "=r"(u) : "f"(x));
    return u;
}
__device__ __forceinline__ float rnd1(float x) { return __uint_as_float(f2tf32(x)); }
__device__ __forceinline__ float4 rnd4(float4 v) {
    v.x = rnd1(v.x); v.y = rnd1(v.y); v.z = rnd1(v.z); v.w = rnd1(v.w);
    return v;
}
__device__ __forceinline__ void ldsm4(uint32_t a, uint32_t r[4]) {
    asm volatile("ldmatrix.sync.aligned.m8n8.x4.shared.b16 {%0,%1,%2,%3}, [%4];"
                 : "=r"(r[0]), "=r"(r[1]), "=r"(r[2]), "=r"(r[3]) : "r"(a));
}
__device__ __forceinline__ void cpa16(uint32_t dst, const void* src) {
    asm volatile("cp.async.cg.shared.global [%0], [%1], 16;" :: "r"(dst), "l"(src));
}

// =====================================================================
// att_cp: att[m][b][o] = sum_k A[b][k]*B[o][k] + bc[m][o]
//   A = [fea_z (384) | g_rounded[:,m,:] (768)]   (all pre-rounded to tf32)
//   B = [Wc[m] (384) | WB[m] (768)]
// Tile 256x128x32, 512 threads (warps 4x4, warp tile 64x32),
// 3-stage cp.async pipeline, XOR-swizzled 128B smem rows, ldmatrix feeds.
// =====================================================================
#define AT_STAGE 49152          // 32768 (A) + 16384 (B) bytes per stage
__global__ __launch_bounds__(512) void att_cp(
    const float* __restrict__ fea_z,
    const float* __restrict__ gr,
    const float* __restrict__ Wc,
    const float* __restrict__ WB,
    const float* __restrict__ bc,
    float* __restrict__ att)
{
    extern __shared__ char smraw[];
    const uint32_t sbase = (uint32_t)__cvta_generic_to_shared(smraw);
    const int tid = threadIdx.x;
    const int m  = blockIdx.z;
    const int bm = blockIdx.y * 256;
    const int bn = blockIdx.x * 128;

    const float* A1 = gr + (size_t)m * DIMF;
    const float* B0 = Wc + (size_t)m * DIMF * DD;
    const float* B1 = WB + (size_t)m * DIMF * DIMF;

    // cp.async per-thread coords
    const int arow = tid >> 3;          // A: rows handled at +0,+64,+128,+192
    const int ach  = tid & 7;           // 16B chunk within 128B row
    const int KT = GW / 32;             // 36

    auto issue = [&](int kt) {
        const int s = kt - (kt / 3) * 3;
        const uint32_t Ab = sbase + s * AT_STAGE;
        const uint32_t Bb = Ab + 32768;
        const int kb = kt * 32;
        const bool seg0 = kb < DD;
        const int ca = seg0 ? (kb + ach * 4) : (kb - DD + ach * 4);
#pragma unroll
        for (int i = 0; i < 4; i++) {
            const int row = arow + i * 64;
            const float* src = seg0 ? (fea_z + (size_t)(bm + row) * DD + ca)
                                    : (A1 + (size_t)(bm + row) * XROW + ca);
            cpa16(Ab + row * 128 + ((ach ^ (row & 7)) * 16), src);
        }
#pragma unroll
        for (int i = 0; i < 2; i++) {
            const int row = (tid >> 3) + i * 64;   // 0..127
            const float* src = seg0 ? (B0 + (size_t)(bn + row) * DD + ca)
                                    : (B1 + (size_t)(bn + row) * DIMF + ca);
            cpa16(Bb + row * 128 + ((ach ^ (row & 7)) * 16), src);
        }
        asm volatile("cp.async.commit_group;" ::: "memory");
    };

    const int warp = tid >> 5, lane = tid & 31;
    const int wm = warp & 3, wn = warp >> 2;
    const int lr = lane >> 2, lc = lane & 3;

    // ldmatrix lane addressing (row&7 == lane&7 for all fragments)
    const int l7 = lane & 7;
    // A: matrix j: rows r+((lane>>3)&1)*8+l7, chunk ks*2+(lane>>4)
    const int a_row_base = wm * 64 + ((lane >> 3) & 1) * 8 + l7;
    // B: rows wn*32 + np*16 + (lane>>4)*8 + l7, chunk ks*2+((lane>>3)&1)
    const int b_row_base = wn * 32 + (lane >> 4) * 8 + l7;
    const int a_chsel = (lane >> 4);
    const int b_chsel = ((lane >> 3) & 1);

    float c[4][4][4];
#pragma unroll
    for (int a = 0; a < 4; a++)
#pragma unroll
        for (int b = 0; b < 4; b++)
#pragma unroll
            for (int d = 0; d < 4; d++) c[a][b][d] = 0.f;

    issue(0);
    issue(1);

    for (int kt = 0; kt < KT; kt++) {
        if (kt + 2 < KT)
            asm volatile("cp.async.wait_group 1;" ::: "memory");
        else
            asm volatile("cp.async.wait_group 0;" ::: "memory");
        __syncthreads();

        const int s = kt - (kt / 3) * 3;
        const uint32_t Ab = sbase + s * AT_STAGE;
        const uint32_t Bb = Ab + 32768;
#pragma unroll
        for (int ks = 0; ks < 4; ks++) {
            uint32_t af[4][4];
#pragma unroll
            for (int mi = 0; mi < 4; mi++) {
                const int row = a_row_base + mi * 16;
                ldsm4(Ab + row * 128 + (((ks * 2 + a_chsel) ^ l7) * 16), af[mi]);
            }
            uint32_t bf[2][4];
#pragma unroll
            for (int np = 0; np < 2; np++) {
                const int row = b_row_base + np * 16;
                ldsm4(Bb + row * 128 + (((ks * 2 + b_chsel) ^ l7) * 16), bf[np]);
            }
#pragma unroll
            for (int np = 0; np < 2; np++)
#pragma unroll
                for (int sb = 0; sb < 2; sb++) {
                    const int ni = np * 2 + sb;
#pragma unroll
                    for (int mi = 0; mi < 4; mi++)
                        asm volatile(
                            "mma.sync.aligned.m16n8k8.row.col.f32.tf32.tf32.f32 "
                            "{%0,%1,%2,%3},{%4,%5,%6,%7},{%8,%9},{%0,%1,%2,%3};\n"
                            : "+f"(c[mi][ni][0]), "+f"(c[mi][ni][1]),
                              "+f"(c[mi][ni][2]), "+f"(c[mi][ni][3])
                            : "r"(af[mi][0]), "r"(af[mi][1]),
                              "r"(af[mi][2]), "r"(af[mi][3]),
                              "r"(bf[np][2 * sb]), "r"(bf[np][2 * sb + 1]));
                }
        }
        if (kt + 2 < KT) issue(kt + 2);
    }

    // epilogue: bias + store (float2)
    float bl[4][2];
#pragma unroll
    for (int ni = 0; ni < 4; ni++) {
        const int col = bn + wn * 32 + ni * 8 + 2 * lc;
        bl[ni][0] = bc[(size_t)m * DIMF + col];
        bl[ni][1] = bc[(size_t)m * DIMF + col + 1];
    }
    float* Cm = att + (size_t)m * BSZ * DIMF;
#pragma unroll
    for (int mi = 0; mi < 4; mi++) {
        const int row = bm + wm * 64 + mi * 16 + lr;
#pragma unroll
        for (int ni = 0; ni < 4; ni++) {
            const int col = bn + wn * 32 + ni * 8 + 2 * lc;
            float2 v0 = make_float2(c[mi][ni][0] + bl[ni][0], c[mi][ni][1] + bl[ni][1]);
            float2 v1 = make_float2(c[mi][ni][2] + bl[ni][0], c[mi][ni][3] + bl[ni][1]);
            *(float2*)(Cm + (size_t)row * DIMF + col) = v0;
            *(float2*)(Cm + (size_t)(row + 8) * DIMF + col) = v1;
        }
    }
}

// ---------------- generic tf32 NT GEMM (mma.sync + ldmatrix) ----------------
template<int MODE, int RND>
__global__ __launch_bounds__(256, 2) void gemm2(
    const float* __restrict__ A0, long sA0z, int lda0, int K0,
    const float* __restrict__ A1, long sA1z, int lda1, int K1,
    const float* __restrict__ B0, long sB0z, int ldb0,
    const float* __restrict__ B1, long sB1z, int ldb1,
    const float* __restrict__ bias, long sBiasZ,
    const float* __restrict__ bng, const float* __restrict__ bnb,
    float* __restrict__ C, long sCz, int N)
{
    const int K  = K0 + K1;
    const int KT = K >> 5;

    extern __shared__ float sm[];
    float* As  = sm;
    float* Bsm = sm + 2 * 128 * 36;

    const int tid = threadIdx.x;
    const int z   = blockIdx.z;
    A0 += z * sA0z;
    if (A1) A1 += z * sA1z;
    B0 += z * sB0z;
    if (B1) B1 += z * sB1z;
    if (bias) bias += z * sBiasZ;
    C  += z * sCz;

    const int bm = blockIdx.y * 128;
    const int bn = blockIdx.x * 128;

    const int lrow = tid >> 3;
    const int c4   = (tid & 7) * 4;

    float4 a_stg[4], b_stg[4];

    auto ldTiles = [&](int kt) {
        const int gk = kt * 32 + c4;
#pragma unroll
        for (int i = 0; i < 4; i++) {
            const int row = lrow + i * 32;
            const float* s = (gk < K0) ? (A0 + (long)(bm + row) * lda0 + gk)
                                       : (A1 + (long)(bm + row) * lda1 + (gk - K0));
            a_stg[i] = *(const float4*)s;
        }
#pragma unroll
        for (int i = 0; i < 4; i++) {
            const int row = lrow + i * 32;
            int j = bn + row; if (j > N - 1) j = N - 1;
            const float* s = (gk < K0) ? (B0 + (long)j * ldb0 + gk)
                                       : (B1 + (long)j * ldb1 + (gk - K0));
            b_stg[i] = *(const float4*)s;
        }
    };
    auto stTiles = [&](int buf) {
        float* a = As  + buf * 128 * 36;
        float* b = Bsm + buf * 128 * 36;
#pragma unroll
        for (int i = 0; i < 4; i++)
            *(float4*)(a + (lrow + i * 32) * 36 + c4) = rnd4(a_stg[i]);
#pragma unroll
        for (int i = 0; i < 4; i++)
            *(float4*)(b + (lrow + i * 32) * 36 + c4) = rnd4(b_stg[i]);
    };

    float c[2][8][4];
#pragma unroll
    for (int a = 0; a < 2; a++)
#pragma unroll
        for (int b2 = 0; b2 < 8; b2++)
#pragma unroll
            for (int d = 0; d < 4; d++) c[a][b2][d] = 0.f;

    const int warp = tid >> 5, lane = tid & 31;
    const int wm = warp & 3, wn = warp >> 2;
    const int lr = lane >> 2, lc = lane & 3;

    const int a_row = wm * 32 + ((lane >> 3) & 1) * 8 + (lane & 7);
    const int a_col = (lane >> 4) * 4;
    const uint32_t aoff = (uint32_t)((a_row * 36 + a_col) * 4);
    const int b_row = wn * 64 + (lane >> 4) * 8 + (lane & 7);
    const int b_col = ((lane >> 3) & 1) * 4;
    const uint32_t boff = (uint32_t)((b_row * 36 + b_col) * 4);

    const uint32_t sA = (uint32_t)__cvta_generic_to_shared(As);
    const uint32_t sB = (uint32_t)__cvta_generic_to_shared(Bsm);
    const uint32_t BUF = 128 * 36 * 4;

    ldTiles(0);
    stTiles(0);
    __syncthreads();

    for (int kt = 0; kt < KT; kt++) {
        const bool has_next = (kt + 1 < KT);
        if (has_next) ldTiles(kt + 1);

        const uint32_t aBuf = sA + (kt & 1) * BUF + aoff;
        const uint32_t bBuf = sB + (kt & 1) * BUF + boff;
#pragma unroll
        for (int ks = 0; ks < 4; ks++) {
            const uint32_t kByte = (uint32_t)(ks * 8 * 4);
            uint32_t af[2][4];
#pragma unroll
            for (int mi = 0; mi < 2; mi++)
                ldsm4(aBuf + mi * (16 * 36 * 4) + kByte, af[mi]);
            uint32_t bf[4][4];
#pragma unroll
            for (int np = 0; np < 4; np++)
                ldsm4(bBuf + np * (16 * 36 * 4) + kByte, bf[np]);
#pragma unroll
            for (int np = 0; np < 4; np++)
#pragma unroll
                for (int s = 0; s < 2; s++) {
                    const int ni = np * 2 + s;
#pragma unroll
                    for (int mi = 0; mi < 2; mi++)
                        asm volatile(
                            "mma.sync.aligned.m16n8k8.row.col.f32.tf32.tf32.f32 "
                            "{%0,%1,%2,%3},{%4,%5,%6,%7},{%8,%9},{%0,%1,%2,%3};\n"
                            : "+f"(c[mi][ni][0]), "+f"(c[mi][ni][1]),
                              "+f"(c[mi][ni][2]), "+f"(c[mi][ni][3])
                            : "r"(af[mi][0]), "r"(af[mi][1]),
                              "r"(af[mi][2]), "r"(af[mi][3]),
                              "r"(bf[np][2 * s]), "r"(bf[np][2 * s + 1]));
                }
        }
        if (has_next) stTiles((kt + 1) & 1);
        __syncthreads();
    }

    const float inv = rsqrtf(1.0f + 1e-5f);
#pragma unroll
    for (int mi = 0; mi < 2; mi++) {
        const int row = bm + wm * 32 + mi * 16 + lr;
#pragma unroll
        for (int ni = 0; ni < 8; ni++) {
            const int col = bn + wn * 64 + ni * 8 + 2 * lc;
#pragma unroll
            for (int h = 0; h < 2; h++) {
                const int r = row + h * 8;
#pragma unroll
                for (int q = 0; q < 2; q++) {
                    const int j = col + q;
                    if (j < N) {
                        float v = c[mi][ni][h * 2 + q];
                        if (bias) v += bias[j];
                        if (MODE == 1) v = fmaxf(v, 0.f) * bng[j] * inv + bnb[j];
                        if (RND) v = rnd1(v);
                        C[(long)r * N + j] = v;
                    }
                }
            }
        }
    }
}

// ---------------- fea_u = sum over the 19 branches of x ----------------
__global__ void reduce_x(const float* __restrict__ x, float* __restrict__ out) {
    long idx = (long)blockIdx.x * blockDim.x + threadIdx.x;
    if (idx >= (long)BSZ * DIMF) return;
    int b = (int)(idx / DIMF);
    int d = (int)(idx % DIMF);
    const float* p = x + (long)b * XROW + d;
    float s = 0.f;
#pragma unroll
    for (int mm = 0; mm < NBR; mm++) s += p[mm * DIMF];
    out[idx] = s;
}

// ---------------- tf32-round g into g_gr ----------------
__global__ void round_g(const float* __restrict__ g, float* __restrict__ out) {
    long i = (long)blockIdx.x * blockDim.x + threadIdx.x;
    if (i >= (long)BSZ * XROW / 4) return;
    ((float4*)out)[i] = rnd4(((const float4*)g)[i]);
}

// ---------------- tf32-round the gfcsB slice into g_WB ----------------
__global__ void round_wb(const float* __restrict__ gfcsW, float* __restrict__ wb) {
    long i = (long)blockIdx.x * blockDim.x + threadIdx.x;   // float4 index
    if (i >= (long)NBR * DIMF * DIMF / 4) return;
    long j4   = i % (DIMF / 4);
    long rowg = i / (DIMF / 4);       // m*768 + o
    const float4 v = *(const float4*)(gfcsW + rowg * GW + DD + j4 * 4);
    ((float4*)wb)[i] = rnd4(v);
}

// ---------------- setup: transpose fcs_W  +  folded bias (merged) ----------------
__global__ void setup_misc(const float* __restrict__ fcsW, float* __restrict__ fcsT,
                           const float* __restrict__ gfcsW, const float* __restrict__ gfcsB,
                           const float* __restrict__ fcsB, float* __restrict__ bc)
{
    const int m = blockIdx.z;
    if (blockIdx.y < 12) {
        __shared__ float t[32][33];
        const int i0 = blockIdx.y * 32, d0 = blockIdx.x * 32;
        const float* src = fcsW + (size_t)m * DD * DD;
        float* dst       = fcsT + (size_t)m * DD * DD;
        const int x = threadIdx.x, y = threadIdx.y;
#pragma unroll
        for (int yy = y; yy < 32; yy += 8)
            t[yy][x] = src[(size_t)(i0 + yy) * DD + d0 + x];
        __syncthreads();
#pragma unroll
        for (int yy = y; yy < 32; yy += 8)
            dst[(size_t)(d0 + yy) * DD + i0 + x] = t[x][yy];
    } else {
        const int tid = threadIdx.y * 32 + threadIdx.x;
        const int w = tid >> 5, lane = tid & 31;
        const float* fb = fcsB + m * DD;
        for (int j = 0; j < 8; j++) {
            const int o = blockIdx.x * 64 + w * 8 + j;
            const float* wp = gfcsW + ((size_t)m * DIMF + o) * GW;
            float s = 0.f;
            for (int i = lane; i < DD; i += 32) s += wp[i] * fb[i];
#pragma unroll
            for (int off = 16; off; off >>= 1) s += __shfl_xor_sync(0xffffffffu, s, off);
            if (lane == 0) bc[(size_t)m * DIMF + o] = s + gfcsB[(size_t)m * DIMF + o];
        }
    }
}

// ---------------- softmax over m + weighted sum with x ----------------
__global__ void softmax_wsum(const float* __restrict__ att,
                             const float* __restrict__ x,
                             float* __restrict__ out) {
    long idx = (long)blockIdx.x * blockDim.x + threadIdx.x;
    if (idx >= (long)BSZ * DIMF) return;
    int b = (int)(idx / DIMF);
    int o = (int)(idx % DIMF);
    float v[NBR];
    float mx = -1e30f;
#pragma unroll
    for (int mm = 0; mm < NBR; mm++) {
        v[mm] = att[((long)mm * BSZ + b) * DIMF + o];
        mx = fmaxf(mx, v[mm]);
    }
    float s = 0.f;
#pragma unroll
    for (int mm = 0; mm < NBR; mm++) { v[mm] = expf(v[mm] - mx); s += v[mm]; }
    const float invs = 1.f / s;
    float acc = 0.f;
    const float* xp = x + (long)b * XROW + o;
#pragma unroll
    for (int mm = 0; mm < NBR; mm++) acc += v[mm] * invs * xp[mm * DIMF];
    out[idx] = acc;
}

// ---------------- launch ----------------
extern "C" void kernel_launch(void* const* d_in, const int* in_sizes, int n_in,
                              void* d_out, int out_size) {
    const float* x      = (const float*)d_in[0];
    const float* g      = (const float*)d_in[1];
    const float* fc1_W  = (const float*)d_in[2];
    const float* fc1_b  = (const float*)d_in[3];
    const float* bn1_g  = (const float*)d_in[4];
    const float* bn1_b  = (const float*)d_in[5];
    const float* fc2_W  = (const float*)d_in[6];
    const float* fc2_b  = (const float*)d_in[7];
    const float* fcs_W  = (const float*)d_in[8];
    const float* fcs_b  = (const float*)d_in[9];
    const float* gfcs_W = (const float*)d_in[10];
    const float* gfcs_b = (const float*)d_in[11];
    const float* l1_W   = (const float*)d_in[12];
    const float* l1_b   = (const float*)d_in[13];
    const float* bna_g  = (const float*)d_in[14];
    const float* bna_b  = (const float*)d_in[15];
    const float* l2_W   = (const float*)d_in[16];
    const float* l2_b   = (const float*)d_in[17];
    const float* bnb_g  = (const float*)d_in[18];
    const float* bnb_b  = (const float*)d_in[19];
    const float* l3_W   = (const float*)d_in[20];
    const float* l3_b   = (const float*)d_in[21];
    float* out = (float*)d_out;

    float *fea_u, *h1, *fea_z, *att, *fea_v, *hA, *hB, *Wc, *fcsT, *bc, *gr, *WB;
    cudaGetSymbolAddress((void**)&fea_u, g_fea_u);
    cudaGetSymbolAddress((void**)&h1,    g_h1);
    cudaGetSymbolAddress((void**)&fea_z, g_fea_z);
    cudaGetSymbolAddress((void**)&att,   g_att);
    cudaGetSymbolAddress((void**)&fea_v, g_fea_v);
    cudaGetSymbolAddress((void**)&hA,    g_hA);
    cudaGetSymbolAddress((void**)&hB,    g_hB);
    cudaGetSymbolAddress((void**)&Wc,    g_Wc);
    cudaGetSymbolAddress((void**)&fcsT,  g_fcsT);
    cudaGetSymbolAddress((void**)&bc,    g_bc);
    cudaGetSymbolAddress((void**)&gr,    g_gr);
    cudaGetSymbolAddress((void**)&WB,    g_WB);

    const int SMEM  = 2 * 2 * 128 * 36 * 4;   // gemm2: 73728 B
    const int ASMEM = 3 * AT_STAGE;           // att_cp: 147456 B
    cudaFuncSetAttribute(gemm2<0,0>, cudaFuncAttributeMaxDynamicSharedMemorySize, SMEM);
    cudaFuncSetAttribute(gemm2<0,1>, cudaFuncAttributeMaxDynamicSharedMemorySize, SMEM);
    cudaFuncSetAttribute(gemm2<1,0>, cudaFuncAttributeMaxDynamicSharedMemorySize, SMEM);
    cudaFuncSetAttribute(att_cp,     cudaFuncAttributeMaxDynamicSharedMemorySize, ASMEM);

    // setup / pre-rounding
    setup_misc<<<dim3(12, 13, NBR), dim3(32, 8)>>>(fcs_W, fcsT, gfcs_W, gfcs_b, fcs_b, bc);
    round_g<<<(int)(((long)BSZ * XROW / 4 + 255) / 256), 256>>>(g, gr);
    round_wb<<<(int)(((long)NBR * DIMF * DIMF / 4 + 255) / 256), 256>>>(gfcs_W, WB);

    // Wc[m] = gfcsA[m] @ fcs_W[m]  (tf32-rounded output)
    gemm2<0,1><<<dim3(3, 6, NBR), 256, SMEM>>>(
        gfcs_W, (long)DIMF * GW, GW, DD,  nullptr, 0, 0, 0,
        fcsT, (long)DD * DD, DD,  nullptr, 0, 0,
        nullptr, 0, nullptr, nullptr,
        Wc, (long)DIMF * DD, DD);

    // fea_u = sum_m x
    reduce_x<<<(BSZ * DIMF + 255) / 256, 256>>>(x, fea_u);

    // h1 = BN(ReLU(fea_u @ fc1^T + b))
    gemm2<1,0><<<dim3(3, 32, 1), 256, SMEM>>>(
        fea_u, 0, DIMF, DIMF,  nullptr, 0, 0, 0,
        fc1_W, 0, DIMF,  nullptr, 0, 0,
        fc1_b, 0, bn1_g, bn1_b, h1, 0, DD);

    // fea_z = h1 @ fc2^T + b   (tf32-rounded output)
    gemm2<0,1><<<dim3(3, 32, 1), 256, SMEM>>>(
        h1, 0, DD, DD,  nullptr, 0, 0, 0,
        fc2_W, 0, DD,  nullptr, 0, 0,
        fc2_b, 0, nullptr, nullptr, fea_z, 0, DD);

    // att (cp.async pipelined tensor GEMM)
    att_cp<<<dim3(6, 16, NBR), 512, ASMEM>>>(fea_z, gr, Wc, WB, bc, att);

    // softmax over m + weighted sum with x
    softmax_wsum<<<(BSZ * DIMF + 255) / 256, 256>>>(att, x, fea_v);

    // classifier head
    gemm2<1,0><<<dim3(1, 32, 1), 256, SMEM>>>(
        fea_v, 0, DIMF, DIMF,  nullptr, 0, 0, 0,
        l1_W, 0, DIMF,  nullptr, 0, 0,
        l1_b, 0, bna_g, bna_b, hA, 0, 128);

    gemm2<1,0><<<dim3(1, 32, 1), 256, SMEM>>>(
        hA, 0, 128, 128,  nullptr, 0, 0, 0,
        l2_W, 0, 128,  nullptr, 0, 0,
        l2_b, 0, bnb_g, bnb_b, hB, 0, 32);

    gemm2<0,0><<<dim3(1, 32, 1), 256, SMEM>>>(
        hB, 0, 32, 32,  nullptr, 0, 0, 0,
        l3_W, 0, 32,  nullptr, 0, 0,
        l3_b, 0, nullptr, nullptr, out, 0, 20);
}

// round 8
// speedup vs baseline: 1.3217x; 1.0125x over previous
#include <cuda_runtime.h>
#include <cstdint>

#define NBR   19
#define DIMF  768
#define DD    384
#define BSZ   4096
#define XROW  (NBR * DIMF)   // 14592
#define GW    (DIMF + DD)    // 1152

// ---------------- scratch (device globals) ----------------
__device__ float g_fea_u[(size_t)BSZ * DIMF];
__device__ float g_h1[(size_t)BSZ * DD];
__device__ float g_fea_z[(size_t)BSZ * DD];
__device__ float g_att[(size_t)NBR * BSZ * DIMF];
__device__ float g_fea_v[(size_t)BSZ * DIMF];
__device__ float g_hA[(size_t)BSZ * 128];
__device__ float g_hB[(size_t)BSZ * 32];
__device__ float g_Wc[(size_t)NBR * DIMF * DD];
__device__ float g_fcsT[(size_t)NBR * DD * DD];
__device__ float g_bc[(size_t)NBR * DIMF];
__device__ float g_gr[(size_t)BSZ * XROW];          // tf32-rounded g
__device__ float g_WB[(size_t)NBR * DIMF * DIMF];   // tf32-rounded gfcsB

// ---------------- helpers ----------------
__device__ __forceinline__ uint32_t f2tf32(float x) {
    uint32_t u;
    asm("cvt.rna.tf32.f32 %0, %1;" : "=r"(u) : "f"(x));
    return u;
}
__device__ __forceinline__ float rnd1(float x) { return __uint_as_float(f2tf32(x)); }
__device__ __forceinline__ float4 rnd4(float4 v) {
    v.x = rnd1(v.x); v.y = rnd1(v.y); v.z = rnd1(v.z); v.w = rnd1(v.w);
    return v;
}
__device__ __forceinline__ void ldsm4(uint32_t a, uint32_t r[4]) {
    asm volatile("ldmatrix.sync.aligned.m8n8.x4.shared.b16 {%0,%1,%2,%3}, [%4];"
                 : "=r"(r[0]), "=r"(r[1]), "=r"(r[2]), "=r"(r[3]) : "r"(a));
}
__device__ __forceinline__ void cpa16(uint32_t dst, const void* src) {
    asm volatile("cp.async.cg.shared.global [%0], [%1], 16;" :: "r"(dst), "l"(src));
}

// =====================================================================
// att_cp: att[m][b][o] = sum_k A[b][k]*B[o][k] + bc[m][o]
//   A = [fea_z (384) | g_rounded[:,m,:] (768)]   (all pre-rounded to tf32)
//   B = [Wc[m] (384) | WB[m] (768)]
// Tile 256x128x32, 512 threads (warps 4x4, warp tile 64x32),
// 4-stage cp.async pipeline, XOR-swizzled 128B smem rows, ldmatrix feeds.
// =====================================================================
#define AT_STAGE 49152          // 32768 (A) + 16384 (B) bytes per stage
__global__ __launch_bounds__(512) void att_cp(
    const float* __restrict__ fea_z,
    const float* __restrict__ gr,
    const float* __restrict__ Wc,
    const float* __restrict__ WB,
    const float* __restrict__ bc,
    float* __restrict__ att)
{
    extern __shared__ char smraw[];
    const uint32_t sbase = (uint32_t)__cvta_generic_to_shared(smraw);
    const int tid = threadIdx.x;
    const int m  = blockIdx.z;
    const int bm = blockIdx.y * 256;
    const int bn = blockIdx.x * 128;

    const float* A1 = gr + (size_t)m * DIMF;
    const float* B0 = Wc + (size_t)m * DIMF * DD;
    const float* B1 = WB + (size_t)m * DIMF * DIMF;

    const int arow = tid >> 3;          // A rows at +0,+64,+128,+192
    const int ach  = tid & 7;           // 16B chunk within 128B row
    const int KT = GW / 32;             // 36

    auto issue = [&](int kt) {
        const int s = kt & 3;
        const uint32_t Ab = sbase + s * AT_STAGE;
        const uint32_t Bb = Ab + 32768;
        const int kb = kt * 32;
        const bool seg0 = kb < DD;
        const int ca = seg0 ? (kb + ach * 4) : (kb - DD + ach * 4);
#pragma unroll
        for (int i = 0; i < 4; i++) {
            const int row = arow + i * 64;
            const float* src = seg0 ? (fea_z + (size_t)(bm + row) * DD + ca)
                                    : (A1 + (size_t)(bm + row) * XROW + ca);
            cpa16(Ab + row * 128 + ((ach ^ (row & 7)) * 16), src);
        }
#pragma unroll
        for (int i = 0; i < 2; i++) {
            const int row = (tid >> 3) + i * 64;   // 0..127
            const float* src = seg0 ? (B0 + (size_t)(bn + row) * DD + ca)
                                    : (B1 + (size_t)(bn + row) * DIMF + ca);
            cpa16(Bb + row * 128 + ((ach ^ (row & 7)) * 16), src);
        }
        asm volatile("cp.async.commit_group;" ::: "memory");
    };

    const int warp = tid >> 5, lane = tid & 31;
    const int wm = warp & 3, wn = warp >> 2;
    const int lr = lane >> 2, lc = lane & 3;

    const int l7 = lane & 7;
    const int a_row_base = wm * 64 + ((lane >> 3) & 1) * 8 + l7;
    const int b_row_base = wn * 32 + (lane >> 4) * 8 + l7;
    const int a_chsel = (lane >> 4);
    const int b_chsel = ((lane >> 3) & 1);

    float c[4][4][4];
#pragma unroll
    for (int a = 0; a < 4; a++)
#pragma unroll
        for (int b = 0; b < 4; b++)
#pragma unroll
            for (int d = 0; d < 4; d++) c[a][b][d] = 0.f;

    issue(0);
    issue(1);
    issue(2);

    for (int kt = 0; kt < KT; kt++) {
        // wait until stage kt is complete (pending <= last_issued - kt)
        if (kt + 2 <= KT - 1)
            asm volatile("cp.async.wait_group 2;" ::: "memory");
        else if (kt + 1 <= KT - 1)
            asm volatile("cp.async.wait_group 1;" ::: "memory");
        else
            asm volatile("cp.async.wait_group 0;" ::: "memory");
        __syncthreads();

        if (kt + 3 < KT) issue(kt + 3);   // early issue: loads fly during MMAs

        const int s = kt & 3;
        const uint32_t Ab = sbase + s * AT_STAGE;
        const uint32_t Bb = Ab + 32768;
#pragma unroll
        for (int ks = 0; ks < 4; ks++) {
            uint32_t af[4][4];
#pragma unroll
            for (int mi = 0; mi < 4; mi++) {
                const int row = a_row_base + mi * 16;
                ldsm4(Ab + row * 128 + (((ks * 2 + a_chsel) ^ l7) * 16), af[mi]);
            }
            uint32_t bf[2][4];
#pragma unroll
            for (int np = 0; np < 2; np++) {
                const int row = b_row_base + np * 16;
                ldsm4(Bb + row * 128 + (((ks * 2 + b_chsel) ^ l7) * 16), bf[np]);
            }
#pragma unroll
            for (int np = 0; np < 2; np++)
#pragma unroll
                for (int sb = 0; sb < 2; sb++) {
                    const int ni = np * 2 + sb;
#pragma unroll
                    for (int mi = 0; mi < 4; mi++)
                        asm volatile(
                            "mma.sync.aligned.m16n8k8.row.col.f32.tf32.tf32.f32 "
                            "{%0,%1,%2,%3},{%4,%5,%6,%7},{%8,%9},{%0,%1,%2,%3};\n"
                            : "+f"(c[mi][ni][0]), "+f"(c[mi][ni][1]),
                              "+f"(c[mi][ni][2]), "+f"(c[mi][ni][3])
                            : "r"(af[mi][0]), "r"(af[mi][1]),
                              "r"(af[mi][2]), "r"(af[mi][3]),
                              "r"(bf[np][2 * sb]), "r"(bf[np][2 * sb + 1]));
                }
        }
    }

    // epilogue: bias + store (float2)
    float bl[4][2];
#pragma unroll
    for (int ni = 0; ni < 4; ni++) {
        const int col = bn + wn * 32 + ni * 8 + 2 * lc;
        bl[ni][0] = bc[(size_t)m * DIMF + col];
        bl[ni][1] = bc[(size_t)m * DIMF + col + 1];
    }
    float* Cm = att + (size_t)m * BSZ * DIMF;
#pragma unroll
    for (int mi = 0; mi < 4; mi++) {
        const int row = bm + wm * 64 + mi * 16 + lr;
#pragma unroll
        for (int ni = 0; ni < 4; ni++) {
            const int col = bn + wn * 32 + ni * 8 + 2 * lc;
            float2 v0 = make_float2(c[mi][ni][0] + bl[ni][0], c[mi][ni][1] + bl[ni][1]);
            float2 v1 = make_float2(c[mi][ni][2] + bl[ni][0], c[mi][ni][3] + bl[ni][1]);
            *(float2*)(Cm + (size_t)row * DIMF + col) = v0;
            *(float2*)(Cm + (size_t)(row + 8) * DIMF + col) = v1;
        }
    }
}

// ---------------- generic tf32 NT GEMM (mma.sync + ldmatrix) ----------------
template<int MODE, int RND>
__global__ __launch_bounds__(256, 2) void gemm2(
    const float* __restrict__ A0, long sA0z, int lda0, int K0,
    const float* __restrict__ A1, long sA1z, int lda1, int K1,
    const float* __restrict__ B0, long sB0z, int ldb0,
    const float* __restrict__ B1, long sB1z, int ldb1,
    const float* __restrict__ bias, long sBiasZ,
    const float* __restrict__ bng, const float* __restrict__ bnb,
    float* __restrict__ C, long sCz, int N)
{
    const int K  = K0 + K1;
    const int KT = K >> 5;

    extern __shared__ float sm[];
    float* As  = sm;
    float* Bsm = sm + 2 * 128 * 36;

    const int tid = threadIdx.x;
    const int z   = blockIdx.z;
    A0 += z * sA0z;
    if (A1) A1 += z * sA1z;
    B0 += z * sB0z;
    if (B1) B1 += z * sB1z;
    if (bias) bias += z * sBiasZ;
    C  += z * sCz;

    const int bm = blockIdx.y * 128;
    const int bn = blockIdx.x * 128;

    const int lrow = tid >> 3;
    const int c4   = (tid & 7) * 4;

    float4 a_stg[4], b_stg[4];

    auto ldTiles = [&](int kt) {
        const int gk = kt * 32 + c4;
#pragma unroll
        for (int i = 0; i < 4; i++) {
            const int row = lrow + i * 32;
            const float* s = (gk < K0) ? (A0 + (long)(bm + row) * lda0 + gk)
                                       : (A1 + (long)(bm + row) * lda1 + (gk - K0));
            a_stg[i] = *(const float4*)s;
        }
#pragma unroll
        for (int i = 0; i < 4; i++) {
            const int row = lrow + i * 32;
            int j = bn + row; if (j > N - 1) j = N - 1;
            const float* s = (gk < K0) ? (B0 + (long)j * ldb0 + gk)
                                       : (B1 + (long)j * ldb1 + (gk - K0));
            b_stg[i] = *(const float4*)s;
        }
    };
    auto stTiles = [&](int buf) {
        float* a = As  + buf * 128 * 36;
        float* b = Bsm + buf * 128 * 36;
#pragma unroll
        for (int i = 0; i < 4; i++)
            *(float4*)(a + (lrow + i * 32) * 36 + c4) = rnd4(a_stg[i]);
#pragma unroll
        for (int i = 0; i < 4; i++)
            *(float4*)(b + (lrow + i * 32) * 36 + c4) = rnd4(b_stg[i]);
    };

    float c[2][8][4];
#pragma unroll
    for (int a = 0; a < 2; a++)
#pragma unroll
        for (int b2 = 0; b2 < 8; b2++)
#pragma unroll
            for (int d = 0; d < 4; d++) c[a][b2][d] = 0.f;

    const int warp = tid >> 5, lane = tid & 31;
    const int wm = warp & 3, wn = warp >> 2;
    const int lr = lane >> 2, lc = lane & 3;

    const int a_row = wm * 32 + ((lane >> 3) & 1) * 8 + (lane & 7);
    const int a_col = (lane >> 4) * 4;
    const uint32_t aoff = (uint32_t)((a_row * 36 + a_col) * 4);
    const int b_row = wn * 64 + (lane >> 4) * 8 + (lane & 7);
    const int b_col = ((lane >> 3) & 1) * 4;
    const uint32_t boff = (uint32_t)((b_row * 36 + b_col) * 4);

    const uint32_t sA = (uint32_t)__cvta_generic_to_shared(As);
    const uint32_t sB = (uint32_t)__cvta_generic_to_shared(Bsm);
    const uint32_t BUF = 128 * 36 * 4;

    ldTiles(0);
    stTiles(0);
    __syncthreads();

    for (int kt = 0; kt < KT; kt++) {
        const bool has_next = (kt + 1 < KT);
        if (has_next) ldTiles(kt + 1);

        const uint32_t aBuf = sA + (kt & 1) * BUF + aoff;
        const uint32_t bBuf = sB + (kt & 1) * BUF + boff;
#pragma unroll
        for (int ks = 0; ks < 4; ks++) {
            const uint32_t kByte = (uint32_t)(ks * 8 * 4);
            uint32_t af[2][4];
#pragma unroll
            for (int mi = 0; mi < 2; mi++)
                ldsm4(aBuf + mi * (16 * 36 * 4) + kByte, af[mi]);
            uint32_t bf[4][4];
#pragma unroll
            for (int np = 0; np < 4; np++)
                ldsm4(bBuf + np * (16 * 36 * 4) + kByte, bf[np]);
#pragma unroll
            for (int np = 0; np < 4; np++)
#pragma unroll
                for (int s = 0; s < 2; s++) {
                    const int ni = np * 2 + s;
#pragma unroll
                    for (int mi = 0; mi < 2; mi++)
                        asm volatile(
                            "mma.sync.aligned.m16n8k8.row.col.f32.tf32.tf32.f32 "
                            "{%0,%1,%2,%3},{%4,%5,%6,%7},{%8,%9},{%0,%1,%2,%3};\n"
                            : "+f"(c[mi][ni][0]), "+f"(c[mi][ni][1]),
                              "+f"(c[mi][ni][2]), "+f"(c[mi][ni][3])
                            : "r"(af[mi][0]), "r"(af[mi][1]),
                              "r"(af[mi][2]), "r"(af[mi][3]),
                              "r"(bf[np][2 * s]), "r"(bf[np][2 * s + 1]));
                }
        }
        if (has_next) stTiles((kt + 1) & 1);
        __syncthreads();
    }

    const float inv = rsqrtf(1.0f + 1e-5f);
#pragma unroll
    for (int mi = 0; mi < 2; mi++) {
        const int row = bm + wm * 32 + mi * 16 + lr;
#pragma unroll
        for (int ni = 0; ni < 8; ni++) {
            const int col = bn + wn * 64 + ni * 8 + 2 * lc;
#pragma unroll
            for (int h = 0; h < 2; h++) {
                const int r = row + h * 8;
#pragma unroll
                for (int q = 0; q < 2; q++) {
                    const int j = col + q;
                    if (j < N) {
                        float v = c[mi][ni][h * 2 + q];
                        if (bias) v += bias[j];
                        if (MODE == 1) v = fmaxf(v, 0.f) * bng[j] * inv + bnb[j];
                        if (RND) v = rnd1(v);
                        C[(long)r * N + j] = v;
                    }
                }
            }
        }
    }
}

// ---------------- fea_u = sum over the 19 branches of x (float4) ----------------
__global__ void reduce_x(const float* __restrict__ x, float* __restrict__ out) {
    long idx = (long)blockIdx.x * blockDim.x + threadIdx.x;   // float4 index
    if (idx >= (long)BSZ * DIMF / 4) return;
    int b  = (int)(idx / (DIMF / 4));
    int d4 = (int)(idx % (DIMF / 4));
    const float4* p = (const float4*)(x + (size_t)b * XROW) + d4;
    float4 s = make_float4(0.f, 0.f, 0.f, 0.f);
#pragma unroll
    for (int mm = 0; mm < NBR; mm++) {
        float4 v = p[mm * (DIMF / 4)];
        s.x += v.x; s.y += v.y; s.z += v.z; s.w += v.w;
    }
    ((float4*)out)[idx] = s;
}

// ---------------- tf32-round g into g_gr ----------------
__global__ void round_g(const float* __restrict__ g, float* __restrict__ out) {
    long i = (long)blockIdx.x * blockDim.x + threadIdx.x;
    if (i >= (long)BSZ * XROW / 4) return;
    ((float4*)out)[i] = rnd4(((const float4*)g)[i]);
}

// ---------------- tf32-round the gfcsB slice into g_WB ----------------
__global__ void round_wb(const float* __restrict__ gfcsW, float* __restrict__ wb) {
    long i = (long)blockIdx.x * blockDim.x + threadIdx.x;   // float4 index
    if (i >= (long)NBR * DIMF * DIMF / 4) return;
    long j4   = i % (DIMF / 4);
    long rowg = i / (DIMF / 4);       // m*768 + o
    const float4 v = *(const float4*)(gfcsW + rowg * GW + DD + j4 * 4);
    ((float4*)wb)[i] = rnd4(v);
}

// ---------------- setup: transpose fcs_W  +  folded bias (merged) ----------------
__global__ void setup_misc(const float* __restrict__ fcsW, float* __restrict__ fcsT,
                           const float* __restrict__ gfcsW, const float* __restrict__ gfcsB,
                           const float* __restrict__ fcsB, float* __restrict__ bc)
{
    const int m = blockIdx.z;
    if (blockIdx.y < 12) {
        __shared__ float t[32][33];
        const int i0 = blockIdx.y * 32, d0 = blockIdx.x * 32;
        const float* src = fcsW + (size_t)m * DD * DD;
        float* dst       = fcsT + (size_t)m * DD * DD;
        const int x = threadIdx.x, y = threadIdx.y;
#pragma unroll
        for (int yy = y; yy < 32; yy += 8)
            t[yy][x] = src[(size_t)(i0 + yy) * DD + d0 + x];
        __syncthreads();
#pragma unroll
        for (int yy = y; yy < 32; yy += 8)
            dst[(size_t)(d0 + yy) * DD + i0 + x] = t[x][yy];
    } else {
        const int tid = threadIdx.y * 32 + threadIdx.x;
        const int w = tid >> 5, lane = tid & 31;
        const float* fb = fcsB + m * DD;
        for (int j = 0; j < 8; j++) {
            const int o = blockIdx.x * 64 + w * 8 + j;
            const float* wp = gfcsW + ((size_t)m * DIMF + o) * GW;
            float s = 0.f;
            for (int i = lane; i < DD; i += 32) s += wp[i] * fb[i];
#pragma unroll
            for (int off = 16; off; off >>= 1) s += __shfl_xor_sync(0xffffffffu, s, off);
            if (lane == 0) bc[(size_t)m * DIMF + o] = s + gfcsB[(size_t)m * DIMF + o];
        }
    }
}

// ---------------- softmax over m + weighted sum with x (float4) ----------------
__global__ void softmax_wsum(const float* __restrict__ att,
                             const float* __restrict__ x,
                             float* __restrict__ out) {
    long idx = (long)blockIdx.x * blockDim.x + threadIdx.x;   // float4 index
    if (idx >= (long)BSZ * DIMF / 4) return;
    int b  = (int)(idx / (DIMF / 4));
    int o4 = (int)(idx % (DIMF / 4));

    float4 v[NBR];
    float4 mx = make_float4(-1e30f, -1e30f, -1e30f, -1e30f);
#pragma unroll
    for (int mm = 0; mm < NBR; mm++) {
        v[mm] = *((const float4*)(att + ((size_t)mm * BSZ + b) * DIMF) + o4);
        mx.x = fmaxf(mx.x, v[mm].x); mx.y = fmaxf(mx.y, v[mm].y);
        mx.z = fmaxf(mx.z, v[mm].z); mx.w = fmaxf(mx.w, v[mm].w);
    }
    float4 s = make_float4(0.f, 0.f, 0.f, 0.f);
#pragma unroll
    for (int mm = 0; mm < NBR; mm++) {
        v[mm].x = __expf(v[mm].x - mx.x); s.x += v[mm].x;
        v[mm].y = __expf(v[mm].y - mx.y); s.y += v[mm].y;
        v[mm].z = __expf(v[mm].z - mx.z); s.z += v[mm].z;
        v[mm].w = __expf(v[mm].w - mx.w); s.w += v[mm].w;
    }
    s.x = 1.f / s.x; s.y = 1.f / s.y; s.z = 1.f / s.z; s.w = 1.f / s.w;
    float4 acc = make_float4(0.f, 0.f, 0.f, 0.f);
    const float4* xp = (const float4*)(x + (size_t)b * XROW) + o4;
#pragma unroll
    for (int mm = 0; mm < NBR; mm++) {
        float4 xv = xp[mm * (DIMF / 4)];
        acc.x += v[mm].x * s.x * xv.x;
        acc.y += v[mm].y * s.y * xv.y;
        acc.z += v[mm].z * s.z * xv.z;
        acc.w += v[mm].w * s.w * xv.w;
    }
    ((float4*)out)[idx] = acc;
}

// ---------------- launch ----------------
extern "C" void kernel_launch(void* const* d_in, const int* in_sizes, int n_in,
                              void* d_out, int out_size) {
    const float* x      = (const float*)d_in[0];
    const float* g      = (const float*)d_in[1];
    const float* fc1_W  = (const float*)d_in[2];
    const float* fc1_b  = (const float*)d_in[3];
    const float* bn1_g  = (const float*)d_in[4];
    const float* bn1_b  = (const float*)d_in[5];
    const float* fc2_W  = (const float*)d_in[6];
    const float* fc2_b  = (const float*)d_in[7];
    const float* fcs_W  = (const float*)d_in[8];
    const float* fcs_b  = (const float*)d_in[9];
    const float* gfcs_W = (const float*)d_in[10];
    const float* gfcs_b = (const float*)d_in[11];
    const float* l1_W   = (const float*)d_in[12];
    const float* l1_b   = (const float*)d_in[13];
    const float* bna_g  = (const float*)d_in[14];
    const float* bna_b  = (const float*)d_in[15];
    const float* l2_W   = (const float*)d_in[16];
    const float* l2_b   = (const float*)d_in[17];
    const float* bnb_g  = (const float*)d_in[18];
    const float* bnb_b  = (const float*)d_in[19];
    const float* l3_W   = (const float*)d_in[20];
    const float* l3_b   = (const float*)d_in[21];
    float* out = (float*)d_out;

    float *fea_u, *h1, *fea_z, *att, *fea_v, *hA, *hB, *Wc, *fcsT, *bc, *gr, *WB;
    cudaGetSymbolAddress((void**)&fea_u, g_fea_u);
    cudaGetSymbolAddress((void**)&h1,    g_h1);
    cudaGetSymbolAddress((void**)&fea_z, g_fea_z);
    cudaGetSymbolAddress((void**)&att,   g_att);
    cudaGetSymbolAddress((void**)&fea_v, g_fea_v);
    cudaGetSymbolAddress((void**)&hA,    g_hA);
    cudaGetSymbolAddress((void**)&hB,    g_hB);
    cudaGetSymbolAddress((void**)&Wc,    g_Wc);
    cudaGetSymbolAddress((void**)&fcsT,  g_fcsT);
    cudaGetSymbolAddress((void**)&bc,    g_bc);
    cudaGetSymbolAddress((void**)&gr,    g_gr);
    cudaGetSymbolAddress((void**)&WB,    g_WB);

    const int SMEM  = 2 * 2 * 128 * 36 * 4;   // gemm2: 73728 B
    const int ASMEM = 4 * AT_STAGE;           // att_cp: 196608 B
    cudaFuncSetAttribute(gemm2<0,0>, cudaFuncAttributeMaxDynamicSharedMemorySize, SMEM);
    cudaFuncSetAttribute(gemm2<0,1>, cudaFuncAttributeMaxDynamicSharedMemorySize, SMEM);
    cudaFuncSetAttribute(gemm2<1,0>, cudaFuncAttributeMaxDynamicSharedMemorySize, SMEM);
    cudaFuncSetAttribute(att_cp,     cudaFuncAttributeMaxDynamicSharedMemorySize, ASMEM);

    // setup / pre-rounding
    setup_misc<<<dim3(12, 13, NBR), dim3(32, 8)>>>(fcs_W, fcsT, gfcs_W, gfcs_b, fcs_b, bc);
    round_g<<<(int)(((long)BSZ * XROW / 4 + 255) / 256), 256>>>(g, gr);
    round_wb<<<(int)(((long)NBR * DIMF * DIMF / 4 + 255) / 256), 256>>>(gfcs_W, WB);

    // Wc[m] = gfcsA[m] @ fcs_W[m]  (tf32-rounded output)
    gemm2<0,1><<<dim3(3, 6, NBR), 256, SMEM>>>(
        gfcs_W, (long)DIMF * GW, GW, DD,  nullptr, 0, 0, 0,
        fcsT, (long)DD * DD, DD,  nullptr, 0, 0,
        nullptr, 0, nullptr, nullptr,
        Wc, (long)DIMF * DD, DD);

    // fea_u = sum_m x
    reduce_x<<<(BSZ * DIMF / 4 + 255) / 256, 256>>>(x, fea_u);

    // h1 = BN(ReLU(fea_u @ fc1^T + b))
    gemm2<1,0><<<dim3(3, 32, 1), 256, SMEM>>>(
        fea_u, 0, DIMF, DIMF,  nullptr, 0, 0, 0,
        fc1_W, 0, DIMF,  nullptr, 0, 0,
        fc1_b, 0, bn1_g, bn1_b, h1, 0, DD);

    // fea_z = h1 @ fc2^T + b   (tf32-rounded output)
    gemm2<0,1><<<dim3(3, 32, 1), 256, SMEM>>>(
        h1, 0, DD, DD,  nullptr, 0, 0, 0,
        fc2_W, 0, DD,  nullptr, 0, 0,
        fc2_b, 0, nullptr, nullptr, fea_z, 0, DD);

    // att (cp.async pipelined tensor GEMM)
    att_cp<<<dim3(6, 16, NBR), 512, ASMEM>>>(fea_z, gr, Wc, WB, bc, att);

    // softmax over m + weighted sum with x
    softmax_wsum<<<(BSZ * DIMF / 4 + 255) / 256, 256>>>(att, x, fea_v);

    // classifier head
    gemm2<1,0><<<dim3(1, 32, 1), 256, SMEM>>>(
        fea_v, 0, DIMF, DIMF,  nullptr, 0, 0, 0,
        l1_W, 0, DIMF,  nullptr, 0, 0,
        l1_b, 0, bna_g, bna_b, hA, 0, 128);

    gemm2<1,0><<<dim3(1, 32, 1), 256, SMEM>>>(
        hA, 0, 128, 128,  nullptr, 0, 0, 0,
        l2_W, 0, 128,  nullptr, 0, 0,
        l2_b, 0, bnb_g, bnb_b, hB, 0, 32);

    gemm2<0,0><<<dim3(1, 32, 1), 256, SMEM>>>(
        hB, 0, 32, 32,  nullptr, 0, 0, 0,
        l3_W, 0, 32,  nullptr, 0, 0,
        l3_b, 0, nullptr, nullptr, out, 0, 20);
}

// round 9
// speedup vs baseline: 1.4157x; 1.0712x over previous
#include <cuda_runtime.h>
#include <cstdint>

#define NBR   19
#define DIMF  768
#define DD    384
#define BSZ   4096
#define XROW  (NBR * DIMF)   // 14592
#define GW    (DIMF + DD)    // 1152

// ---------------- scratch (device globals) ----------------
__device__ float g_fea_u[(size_t)BSZ * DIMF];
__device__ float g_h1[(size_t)BSZ * DD];
__device__ float g_fea_z[(size_t)BSZ * DD];
__device__ float g_att[(size_t)NBR * BSZ * DIMF];
__device__ float g_fea_v[(size_t)BSZ * DIMF];
__device__ float g_hA[(size_t)BSZ * 128];
__device__ float g_hB[(size_t)BSZ * 32];
__device__ float g_Wc[(size_t)NBR * DIMF * DD];
__device__ float g_fcsT[(size_t)NBR * DD * DD];
__device__ float g_bc[(size_t)NBR * DIMF];
__device__ float g_WB[(size_t)NBR * DIMF * DIMF];   // tf32-rounded gfcsB

// ---------------- helpers ----------------
__device__ __forceinline__ uint32_t f2tf32(float x) {
    uint32_t u;
    asm("cvt.rna.tf32.f32 %0, %1;" : "=r"(u) : "f"(x));
    return u;
}
__device__ __forceinline__ float rnd1(float x) { return __uint_as_float(f2tf32(x)); }
__device__ __forceinline__ float4 rnd4(float4 v) {
    v.x = rnd1(v.x); v.y = rnd1(v.y); v.z = rnd1(v.z); v.w = rnd1(v.w);
    return v;
}
__device__ __forceinline__ void ldsm4(uint32_t a, uint32_t r[4]) {
    asm volatile("ldmatrix.sync.aligned.m8n8.x4.shared.b16 {%0,%1,%2,%3}, [%4];"
                 : "=r"(r[0]), "=r"(r[1]), "=r"(r[2]), "=r"(r[3]) : "r"(a));
}
__device__ __forceinline__ void cpa16(uint32_t dst, const void* src) {
    asm volatile("cp.async.cg.shared.global [%0], [%1], 16;" :: "r"(dst), "l"(src));
}

// =====================================================================
// att_cp: att[m][b][o] = sum_k A[b][k]*B[o][k] + bc[m][o]
//   A = [fea_z (384, RNA-rounded) | g[:,m,:] (768, raw fp32 -> HW truncation)]
//   B = [Wc[m] (384, rounded) | WB[m] (768, rounded)]
// Tile 256x128x32, 512 threads (warps 4x4, warp tile 64x32),
// 4-stage cp.async pipeline, XOR-swizzled 128B smem rows, ldmatrix feeds.
// =====================================================================
#define AT_STAGE 49152          // 32768 (A) + 16384 (B) bytes per stage
__global__ __launch_bounds__(512) void att_cp(
    const float* __restrict__ fea_z,
    const float* __restrict__ g,
    const float* __restrict__ Wc,
    const float* __restrict__ WB,
    const float* __restrict__ bc,
    float* __restrict__ att)
{
    extern __shared__ char smraw[];
    const uint32_t sbase = (uint32_t)__cvta_generic_to_shared(smraw);
    const int tid = threadIdx.x;
    const int m  = blockIdx.z;
    const int bm = blockIdx.y * 256;
    const int bn = blockIdx.x * 128;

    const float* A1 = g + (size_t)m * DIMF;
    const float* B0 = Wc + (size_t)m * DIMF * DD;
    const float* B1 = WB + (size_t)m * DIMF * DIMF;

    const int arow = tid >> 3;          // A rows at +0,+64,+128,+192
    const int ach  = tid & 7;           // 16B chunk within 128B row
    const int KT = GW / 32;             // 36

    auto issue = [&](int kt) {
        const int s = kt & 3;
        const uint32_t Ab = sbase + s * AT_STAGE;
        const uint32_t Bb = Ab + 32768;
        const int kb = kt * 32;
        const bool seg0 = kb < DD;
        const int ca = seg0 ? (kb + ach * 4) : (kb - DD + ach * 4);
#pragma unroll
        for (int i = 0; i < 4; i++) {
            const int row = arow + i * 64;
            const float* src = seg0 ? (fea_z + (size_t)(bm + row) * DD + ca)
                                    : (A1 + (size_t)(bm + row) * XROW + ca);
            cpa16(Ab + row * 128 + ((ach ^ (row & 7)) * 16), src);
        }
#pragma unroll
        for (int i = 0; i < 2; i++) {
            const int row = (tid >> 3) + i * 64;   // 0..127
            const float* src = seg0 ? (B0 + (size_t)(bn + row) * DD + ca)
                                    : (B1 + (size_t)(bn + row) * DIMF + ca);
            cpa16(Bb + row * 128 + ((ach ^ (row & 7)) * 16), src);
        }
        asm volatile("cp.async.commit_group;" ::: "memory");
    };

    const int warp = tid >> 5, lane = tid & 31;
    const int wm = warp & 3, wn = warp >> 2;
    const int lr = lane >> 2, lc = lane & 3;

    const int l7 = lane & 7;
    const int a_row_base = wm * 64 + ((lane >> 3) & 1) * 8 + l7;
    const int b_row_base = wn * 32 + (lane >> 4) * 8 + l7;
    const int a_chsel = (lane >> 4);
    const int b_chsel = ((lane >> 3) & 1);

    float c[4][4][4];
#pragma unroll
    for (int a = 0; a < 4; a++)
#pragma unroll
        for (int b = 0; b < 4; b++)
#pragma unroll
            for (int d = 0; d < 4; d++) c[a][b][d] = 0.f;

    issue(0);
    issue(1);
    issue(2);

    for (int kt = 0; kt < KT; kt++) {
        if (kt + 2 <= KT - 1)
            asm volatile("cp.async.wait_group 2;" ::: "memory");
        else if (kt + 1 <= KT - 1)
            asm volatile("cp.async.wait_group 1;" ::: "memory");
        else
            asm volatile("cp.async.wait_group 0;" ::: "memory");
        __syncthreads();

        if (kt + 3 < KT) issue(kt + 3);   // early issue: loads fly during MMAs

        const int s = kt & 3;
        const uint32_t Ab = sbase + s * AT_STAGE;
        const uint32_t Bb = Ab + 32768;
#pragma unroll
        for (int ks = 0; ks < 4; ks++) {
            uint32_t af[4][4];
#pragma unroll
            for (int mi = 0; mi < 4; mi++) {
                const int row = a_row_base + mi * 16;
                ldsm4(Ab + row * 128 + (((ks * 2 + a_chsel) ^ l7) * 16), af[mi]);
            }
            uint32_t bf[2][4];
#pragma unroll
            for (int np = 0; np < 2; np++) {
                const int row = b_row_base + np * 16;
                ldsm4(Bb + row * 128 + (((ks * 2 + b_chsel) ^ l7) * 16), bf[np]);
            }
#pragma unroll
            for (int np = 0; np < 2; np++)
#pragma unroll
                for (int sb = 0; sb < 2; sb++) {
                    const int ni = np * 2 + sb;
#pragma unroll
                    for (int mi = 0; mi < 4; mi++)
                        asm volatile(
                            "mma.sync.aligned.m16n8k8.row.col.f32.tf32.tf32.f32 "
                            "{%0,%1,%2,%3},{%4,%5,%6,%7},{%8,%9},{%0,%1,%2,%3};\n"
                            : "+f"(c[mi][ni][0]), "+f"(c[mi][ni][1]),
                              "+f"(c[mi][ni][2]), "+f"(c[mi][ni][3])
                            : "r"(af[mi][0]), "r"(af[mi][1]),
                              "r"(af[mi][2]), "r"(af[mi][3]),
                              "r"(bf[np][2 * sb]), "r"(bf[np][2 * sb + 1]));
                }
        }
    }

    // epilogue: bias + store (float2)
    float bl[4][2];
#pragma unroll
    for (int ni = 0; ni < 4; ni++) {
        const int col = bn + wn * 32 + ni * 8 + 2 * lc;
        bl[ni][0] = bc[(size_t)m * DIMF + col];
        bl[ni][1] = bc[(size_t)m * DIMF + col + 1];
    }
    float* Cm = att + (size_t)m * BSZ * DIMF;
#pragma unroll
    for (int mi = 0; mi < 4; mi++) {
        const int row = bm + wm * 64 + mi * 16 + lr;
#pragma unroll
        for (int ni = 0; ni < 4; ni++) {
            const int col = bn + wn * 32 + ni * 8 + 2 * lc;
            float2 v0 = make_float2(c[mi][ni][0] + bl[ni][0], c[mi][ni][1] + bl[ni][1]);
            float2 v1 = make_float2(c[mi][ni][2] + bl[ni][0], c[mi][ni][3] + bl[ni][1]);
            *(float2*)(Cm + (size_t)row * DIMF + col) = v0;
            *(float2*)(Cm + (size_t)(row + 8) * DIMF + col) = v1;
        }
    }
}

// ---------------- generic tf32 NT GEMM (mma.sync + ldmatrix) ----------------
template<int MODE, int RND>
__global__ __launch_bounds__(256, 2) void gemm2(
    const float* __restrict__ A0, long sA0z, int lda0, int K0,
    const float* __restrict__ A1, long sA1z, int lda1, int K1,
    const float* __restrict__ B0, long sB0z, int ldb0,
    const float* __restrict__ B1, long sB1z, int ldb1,
    const float* __restrict__ bias, long sBiasZ,
    const float* __restrict__ bng, const float* __restrict__ bnb,
    float* __restrict__ C, long sCz, int N)
{
    const int K  = K0 + K1;
    const int KT = K >> 5;

    extern __shared__ float sm[];
    float* As  = sm;
    float* Bsm = sm + 2 * 128 * 36;

    const int tid = threadIdx.x;
    const int z   = blockIdx.z;
    A0 += z * sA0z;
    if (A1) A1 += z * sA1z;
    B0 += z * sB0z;
    if (B1) B1 += z * sB1z;
    if (bias) bias += z * sBiasZ;
    C  += z * sCz;

    const int bm = blockIdx.y * 128;
    const int bn = blockIdx.x * 128;

    const int lrow = tid >> 3;
    const int c4   = (tid & 7) * 4;

    float4 a_stg[4], b_stg[4];

    auto ldTiles = [&](int kt) {
        const int gk = kt * 32 + c4;
#pragma unroll
        for (int i = 0; i < 4; i++) {
            const int row = lrow + i * 32;
            const float* s = (gk < K0) ? (A0 + (long)(bm + row) * lda0 + gk)
                                       : (A1 + (long)(bm + row) * lda1 + (gk - K0));
            a_stg[i] = *(const float4*)s;
        }
#pragma unroll
        for (int i = 0; i < 4; i++) {
            const int row = lrow + i * 32;
            int j = bn + row; if (j > N - 1) j = N - 1;
            const float* s = (gk < K0) ? (B0 + (long)j * ldb0 + gk)
                                       : (B1 + (long)j * ldb1 + (gk - K0));
            b_stg[i] = *(const float4*)s;
        }
    };
    auto stTiles = [&](int buf) {
        float* a = As  + buf * 128 * 36;
        float* b = Bsm + buf * 128 * 36;
#pragma unroll
        for (int i = 0; i < 4; i++)
            *(float4*)(a + (lrow + i * 32) * 36 + c4) = rnd4(a_stg[i]);
#pragma unroll
        for (int i = 0; i < 4; i++)
            *(float4*)(b + (lrow + i * 32) * 36 + c4) = rnd4(b_stg[i]);
    };

    float c[2][8][4];
#pragma unroll
    for (int a = 0; a < 2; a++)
#pragma unroll
        for (int b2 = 0; b2 < 8; b2++)
#pragma unroll
            for (int d = 0; d < 4; d++) c[a][b2][d] = 0.f;

    const int warp = tid >> 5, lane = tid & 31;
    const int wm = warp & 3, wn = warp >> 2;
    const int lr = lane >> 2, lc = lane & 3;

    const int a_row = wm * 32 + ((lane >> 3) & 1) * 8 + (lane & 7);
    const int a_col = (lane >> 4) * 4;
    const uint32_t aoff = (uint32_t)((a_row * 36 + a_col) * 4);
    const int b_row = wn * 64 + (lane >> 4) * 8 + (lane & 7);
    const int b_col = ((lane >> 3) & 1) * 4;
    const uint32_t boff = (uint32_t)((b_row * 36 + b_col) * 4);

    const uint32_t sA = (uint32_t)__cvta_generic_to_shared(As);
    const uint32_t sB = (uint32_t)__cvta_generic_to_shared(Bsm);
    const uint32_t BUF = 128 * 36 * 4;

    ldTiles(0);
    stTiles(0);
    __syncthreads();

    for (int kt = 0; kt < KT; kt++) {
        const bool has_next = (kt + 1 < KT);
        if (has_next) ldTiles(kt + 1);

        const uint32_t aBuf = sA + (kt & 1) * BUF + aoff;
        const uint32_t bBuf = sB + (kt & 1) * BUF + boff;
#pragma unroll
        for (int ks = 0; ks < 4; ks++) {
            const uint32_t kByte = (uint32_t)(ks * 8 * 4);
            uint32_t af[2][4];
#pragma unroll
            for (int mi = 0; mi < 2; mi++)
                ldsm4(aBuf + mi * (16 * 36 * 4) + kByte, af[mi]);
            uint32_t bf[4][4];
#pragma unroll
            for (int np = 0; np < 4; np++)
                ldsm4(bBuf + np * (16 * 36 * 4) + kByte, bf[np]);
#pragma unroll
            for (int np = 0; np < 4; np++)
#pragma unroll
                for (int s = 0; s < 2; s++) {
                    const int ni = np * 2 + s;
#pragma unroll
                    for (int mi = 0; mi < 2; mi++)
                        asm volatile(
                            "mma.sync.aligned.m16n8k8.row.col.f32.tf32.tf32.f32 "
                            "{%0,%1,%2,%3},{%4,%5,%6,%7},{%8,%9},{%0,%1,%2,%3};\n"
                            : "+f"(c[mi][ni][0]), "+f"(c[mi][ni][1]),
                              "+f"(c[mi][ni][2]), "+f"(c[mi][ni][3])
                            : "r"(af[mi][0]), "r"(af[mi][1]),
                              "r"(af[mi][2]), "r"(af[mi][3]),
                              "r"(bf[np][2 * s]), "r"(bf[np][2 * s + 1]));
                }
        }
        if (has_next) stTiles((kt + 1) & 1);
        __syncthreads();
    }

    const float inv = rsqrtf(1.0f + 1e-5f);
#pragma unroll
    for (int mi = 0; mi < 2; mi++) {
        const int row = bm + wm * 32 + mi * 16 + lr;
#pragma unroll
        for (int ni = 0; ni < 8; ni++) {
            const int col = bn + wn * 64 + ni * 8 + 2 * lc;
#pragma unroll
            for (int h = 0; h < 2; h++) {
                const int r = row + h * 8;
#pragma unroll
                for (int q = 0; q < 2; q++) {
                    const int j = col + q;
                    if (j < N) {
                        float v = c[mi][ni][h * 2 + q];
                        if (bias) v += bias[j];
                        if (MODE == 1) v = fmaxf(v, 0.f) * bng[j] * inv + bnb[j];
                        if (RND) v = rnd1(v);
                        C[(long)r * N + j] = v;
                    }
                }
            }
        }
    }
}

// ---------------- fea_u = sum over the 19 branches of x (float4) ----------------
__global__ void reduce_x(const float* __restrict__ x, float* __restrict__ out) {
    long idx = (long)blockIdx.x * blockDim.x + threadIdx.x;   // float4 index
    if (idx >= (long)BSZ * DIMF / 4) return;
    int b  = (int)(idx / (DIMF / 4));
    int d4 = (int)(idx % (DIMF / 4));
    const float4* p = (const float4*)(x + (size_t)b * XROW) + d4;
    float4 s = make_float4(0.f, 0.f, 0.f, 0.f);
#pragma unroll
    for (int mm = 0; mm < NBR; mm++) {
        float4 v = p[mm * (DIMF / 4)];
        s.x += v.x; s.y += v.y; s.z += v.z; s.w += v.w;
    }
    ((float4*)out)[idx] = s;
}

// ---------------- tf32-round the gfcsB slice into g_WB ----------------
__global__ void round_wb(const float* __restrict__ gfcsW, float* __restrict__ wb) {
    long i = (long)blockIdx.x * blockDim.x + threadIdx.x;   // float4 index
    if (i >= (long)NBR * DIMF * DIMF / 4) return;
    long j4   = i % (DIMF / 4);
    long rowg = i / (DIMF / 4);       // m*768 + o
    const float4 v = *(const float4*)(gfcsW + rowg * GW + DD + j4 * 4);
    ((float4*)wb)[i] = rnd4(v);
}

// ---------------- setup: transpose fcs_W  +  folded bias (merged) ----------------
__global__ void setup_misc(const float* __restrict__ fcsW, float* __restrict__ fcsT,
                           const float* __restrict__ gfcsW, const float* __restrict__ gfcsB,
                           const float* __restrict__ fcsB, float* __restrict__ bc)
{
    const int m = blockIdx.z;
    if (blockIdx.y < 12) {
        __shared__ float t[32][33];
        const int i0 = blockIdx.y * 32, d0 = blockIdx.x * 32;
        const float* src = fcsW + (size_t)m * DD * DD;
        float* dst       = fcsT + (size_t)m * DD * DD;
        const int x = threadIdx.x, y = threadIdx.y;
#pragma unroll
        for (int yy = y; yy < 32; yy += 8)
            t[yy][x] = src[(size_t)(i0 + yy) * DD + d0 + x];
        __syncthreads();
#pragma unroll
        for (int yy = y; yy < 32; yy += 8)
            dst[(size_t)(d0 + yy) * DD + i0 + x] = t[x][yy];
    } else {
        const int tid = threadIdx.y * 32 + threadIdx.x;
        const int w = tid >> 5, lane = tid & 31;
        const float* fb = fcsB + m * DD;
        for (int j = 0; j < 8; j++) {
            const int o = blockIdx.x * 64 + w * 8 + j;
            const float* wp = gfcsW + ((size_t)m * DIMF + o) * GW;
            float s = 0.f;
            for (int i = lane; i < DD; i += 32) s += wp[i] * fb[i];
#pragma unroll
            for (int off = 16; off; off >>= 1) s += __shfl_xor_sync(0xffffffffu, s, off);
            if (lane == 0) bc[(size_t)m * DIMF + o] = s + gfcsB[(size_t)m * DIMF + o];
        }
    }
}

// ---------------- softmax over m + weighted sum with x (float4) ----------------
__global__ void softmax_wsum(const float* __restrict__ att,
                             const float* __restrict__ x,
                             float* __restrict__ out) {
    long idx = (long)blockIdx.x * blockDim.x + threadIdx.x;   // float4 index
    if (idx >= (long)BSZ * DIMF / 4) return;
    int b  = (int)(idx / (DIMF / 4));
    int o4 = (int)(idx % (DIMF / 4));

    float4 v[NBR];
    float4 mx = make_float4(-1e30f, -1e30f, -1e30f, -1e30f);
#pragma unroll
    for (int mm = 0; mm < NBR; mm++) {
        v[mm] = *((const float4*)(att + ((size_t)mm * BSZ + b) * DIMF) + o4);
        mx.x = fmaxf(mx.x, v[mm].x); mx.y = fmaxf(mx.y, v[mm].y);
        mx.z = fmaxf(mx.z, v[mm].z); mx.w = fmaxf(mx.w, v[mm].w);
    }
    float4 s = make_float4(0.f, 0.f, 0.f, 0.f);
#pragma unroll
    for (int mm = 0; mm < NBR; mm++) {
        v[mm].x = __expf(v[mm].x - mx.x); s.x += v[mm].x;
        v[mm].y = __expf(v[mm].y - mx.y); s.y += v[mm].y;
        v[mm].z = __expf(v[mm].z - mx.z); s.z += v[mm].z;
        v[mm].w = __expf(v[mm].w - mx.w); s.w += v[mm].w;
    }
    s.x = 1.f / s.x; s.y = 1.f / s.y; s.z = 1.f / s.z; s.w = 1.f / s.w;
    float4 acc = make_float4(0.f, 0.f, 0.f, 0.f);
    const float4* xp = (const float4*)(x + (size_t)b * XROW) + o4;
#pragma unroll
    for (int mm = 0; mm < NBR; mm++) {
        float4 xv = xp[mm * (DIMF / 4)];
        acc.x += v[mm].x * s.x * xv.x;
        acc.y += v[mm].y * s.y * xv.y;
        acc.z += v[mm].z * s.z * xv.z;
        acc.w += v[mm].w * s.w * xv.w;
    }
    ((float4*)out)[idx] = acc;
}

// ---------------- launch ----------------
extern "C" void kernel_launch(void* const* d_in, const int* in_sizes, int n_in,
                              void* d_out, int out_size) {
    const float* x      = (const float*)d_in[0];
    const float* g      = (const float*)d_in[1];
    const float* fc1_W  = (const float*)d_in[2];
    const float* fc1_b  = (const float*)d_in[3];
    const float* bn1_g  = (const float*)d_in[4];
    const float* bn1_b  = (const float*)d_in[5];
    const float* fc2_W  = (const float*)d_in[6];
    const float* fc2_b  = (const float*)d_in[7];
    const float* fcs_W  = (const float*)d_in[8];
    const float* fcs_b  = (const float*)d_in[9];
    const float* gfcs_W = (const float*)d_in[10];
    const float* gfcs_b = (const float*)d_in[11];
    const float* l1_W   = (const float*)d_in[12];
    const float* l1_b   = (const float*)d_in[13];
    const float* bna_g  = (const float*)d_in[14];
    const float* bna_b  = (const float*)d_in[15];
    const float* l2_W   = (const float*)d_in[16];
    const float* l2_b   = (const float*)d_in[17];
    const float* bnb_g  = (const float*)d_in[18];
    const float* bnb_b  = (const float*)d_in[19];
    const float* l3_W   = (const float*)d_in[20];
    const float* l3_b   = (const float*)d_in[21];
    float* out = (float*)d_out;

    float *fea_u, *h1, *fea_z, *att, *fea_v, *hA, *hB, *Wc, *fcsT, *bc, *WB;
    cudaGetSymbolAddress((void**)&fea_u, g_fea_u);
    cudaGetSymbolAddress((void**)&h1,    g_h1);
    cudaGetSymbolAddress((void**)&fea_z, g_fea_z);
    cudaGetSymbolAddress((void**)&att,   g_att);
    cudaGetSymbolAddress((void**)&fea_v, g_fea_v);
    cudaGetSymbolAddress((void**)&hA,    g_hA);
    cudaGetSymbolAddress((void**)&hB,    g_hB);
    cudaGetSymbolAddress((void**)&Wc,    g_Wc);
    cudaGetSymbolAddress((void**)&fcsT,  g_fcsT);
    cudaGetSymbolAddress((void**)&bc,    g_bc);
    cudaGetSymbolAddress((void**)&WB,    g_WB);

    const int SMEM  = 2 * 2 * 128 * 36 * 4;   // gemm2: 73728 B
    const int ASMEM = 4 * AT_STAGE;           // att_cp: 196608 B
    cudaFuncSetAttribute(gemm2<0,0>, cudaFuncAttributeMaxDynamicSharedMemorySize, SMEM);
    cudaFuncSetAttribute(gemm2<0,1>, cudaFuncAttributeMaxDynamicSharedMemorySize, SMEM);
    cudaFuncSetAttribute(gemm2<1,0>, cudaFuncAttributeMaxDynamicSharedMemorySize, SMEM);
    cudaFuncSetAttribute(att_cp,     cudaFuncAttributeMaxDynamicSharedMemorySize, ASMEM);

    // setup / pre-rounding (weights only; g is fed raw -> HW truncation)
    setup_misc<<<dim3(12, 13, NBR), dim3(32, 8)>>>(fcs_W, fcsT, gfcs_W, gfcs_b, fcs_b, bc);
    round_wb<<<(int)(((long)NBR * DIMF * DIMF / 4 + 255) / 256), 256>>>(gfcs_W, WB);

    // Wc[m] = gfcsA[m] @ fcs_W[m]  (tf32-rounded output)
    gemm2<0,1><<<dim3(3, 6, NBR), 256, SMEM>>>(
        gfcs_W, (long)DIMF * GW, GW, DD,  nullptr, 0, 0, 0,
        fcsT, (long)DD * DD, DD,  nullptr, 0, 0,
        nullptr, 0, nullptr, nullptr,
        Wc, (long)DIMF * DD, DD);

    // fea_u = sum_m x
    reduce_x<<<(BSZ * DIMF / 4 + 255) / 256, 256>>>(x, fea_u);

    // h1 = BN(ReLU(fea_u @ fc1^T + b))
    gemm2<1,0><<<dim3(3, 32, 1), 256, SMEM>>>(
        fea_u, 0, DIMF, DIMF,  nullptr, 0, 0, 0,
        fc1_W, 0, DIMF,  nullptr, 0, 0,
        fc1_b, 0, bn1_g, bn1_b, h1, 0, DD);

    // fea_z = h1 @ fc2^T + b   (tf32-rounded output)
    gemm2<0,1><<<dim3(3, 32, 1), 256, SMEM>>>(
        h1, 0, DD, DD,  nullptr, 0, 0, 0,
        fc2_W, 0, DD,  nullptr, 0, 0,
        fc2_b, 0, nullptr, nullptr, fea_z, 0, DD);

    // att (cp.async pipelined tensor GEMM; g read directly)
    att_cp<<<dim3(6, 16, NBR), 512, ASMEM>>>(fea_z, g, Wc, WB, bc, att);

    // softmax over m + weighted sum with x
    softmax_wsum<<<(BSZ * DIMF / 4 + 255) / 256, 256>>>(att, x, fea_v);

    // classifier head
    gemm2<1,0><<<dim3(1, 32, 1), 256, SMEM>>>(
        fea_v, 0, DIMF, DIMF,  nullptr, 0, 0, 0,
        l1_W, 0, DIMF,  nullptr, 0, 0,
        l1_b, 0, bna_g, bna_b, hA, 0, 128);

    gemm2<1,0><<<dim3(1, 32, 1), 256, SMEM>>>(
        hA, 0, 128, 128,  nullptr, 0, 0, 0,
        l2_W, 0, 128,  nullptr, 0, 0,
        l2_b, 0, bnb_g, bnb_b, hB, 0, 32);

    gemm2<0,0><<<dim3(1, 32, 1), 256, SMEM>>>(
        hB, 0, 32, 32,  nullptr, 0, 0, 0,
        l3_W, 0, 32,  nullptr, 0, 0,
        l3_b, 0, nullptr, nullptr, out, 0, 20);
}

// round 10
// speedup vs baseline: 1.4972x; 1.0575x over previous
#include <cuda_runtime.h>
#include <cstdint>

#define NBR   19
#define DIMF  768
#define DD    384
#define BSZ   4096
#define XROW  (NBR * DIMF)   // 14592
#define GW    (DIMF + DD)    // 1152

// ---------------- scratch (device globals) ----------------
__device__ float g_fea_u[(size_t)BSZ * DIMF];
__device__ float g_h1[(size_t)BSZ * DD];
__device__ float g_fea_z[(size_t)BSZ * DD];
__device__ float g_att[(size_t)NBR * BSZ * DIMF];
__device__ float g_fea_v[(size_t)BSZ * DIMF];
__device__ float g_hA[(size_t)BSZ * 128];
__device__ float g_hB[(size_t)BSZ * 32];
__device__ float g_Wc[(size_t)NBR * DIMF * DD];
__device__ float g_fcsT[(size_t)NBR * DD * DD];
__device__ float g_bc[(size_t)NBR * DIMF];

// ---------------- helpers ----------------
__device__ __forceinline__ uint32_t f2tf32(float x) {
    uint32_t u;
    asm("cvt.rna.tf32.f32 %0, %1;" : "=r"(u) : "f"(x));
    return u;
}
__device__ __forceinline__ float rnd1(float x) { return __uint_as_float(f2tf32(x)); }
__device__ __forceinline__ float4 rnd4(float4 v) {
    v.x = rnd1(v.x); v.y = rnd1(v.y); v.z = rnd1(v.z); v.w = rnd1(v.w);
    return v;
}
__device__ __forceinline__ void ldsm4(uint32_t a, uint32_t r[4]) {
    asm volatile("ldmatrix.sync.aligned.m8n8.x4.shared.b16 {%0,%1,%2,%3}, [%4];"
                 : "=r"(r[0]), "=r"(r[1]), "=r"(r[2]), "=r"(r[3]) : "r"(a));
}
__device__ __forceinline__ void cpa16(uint32_t dst, const void* src) {
    asm volatile("cp.async.cg.shared.global [%0], [%1], 16;" :: "r"(dst), "l"(src));
}

// =====================================================================
// att_cp: att[m][b][o] = sum_k A[b][k]*B[o][k] + bc[m][o]
//   A = [fea_z (384, RNA-rounded) | g[:,m,:] (768, raw -> HW truncation)]
//   B = [Wc[m] (384, rounded) | gfcsB slice of gfcs_W (768, raw -> HW truncation)]
// Tile 256x128x32, 512 threads (warps 4x4, warp tile 64x32),
// 4-stage cp.async pipeline, XOR-swizzled 128B smem rows, ldmatrix feeds.
// =====================================================================
#define AT_STAGE 49152          // 32768 (A) + 16384 (B) bytes per stage
__global__ __launch_bounds__(512) void att_cp(
    const float* __restrict__ fea_z,
    const float* __restrict__ g,
    const float* __restrict__ Wc,
    const float* __restrict__ WB,      // row stride ldb1
    int ldb1,
    const float* __restrict__ bc,
    float* __restrict__ att)
{
    extern __shared__ char smraw[];
    const uint32_t sbase = (uint32_t)__cvta_generic_to_shared(smraw);
    const int tid = threadIdx.x;
    const int m  = blockIdx.z;
    const int bm = blockIdx.y * 256;
    const int bn = blockIdx.x * 128;

    const float* A1 = g + (size_t)m * DIMF;
    const float* B0 = Wc + (size_t)m * DIMF * DD;
    const float* B1 = WB + (size_t)m * DIMF * ldb1;

    const int arow = tid >> 3;          // A rows at +0,+64,+128,+192
    const int ach  = tid & 7;           // 16B chunk within 128B row
    const int KT = GW / 32;             // 36

    auto issue = [&](int kt) {
        const int s = kt & 3;
        const uint32_t Ab = sbase + s * AT_STAGE;
        const uint32_t Bb = Ab + 32768;
        const int kb = kt * 32;
        const bool seg0 = kb < DD;
        const int ca = seg0 ? (kb + ach * 4) : (kb - DD + ach * 4);
#pragma unroll
        for (int i = 0; i < 4; i++) {
            const int row = arow + i * 64;
            const float* src = seg0 ? (fea_z + (size_t)(bm + row) * DD + ca)
                                    : (A1 + (size_t)(bm + row) * XROW + ca);
            cpa16(Ab + row * 128 + ((ach ^ (row & 7)) * 16), src);
        }
#pragma unroll
        for (int i = 0; i < 2; i++) {
            const int row = (tid >> 3) + i * 64;   // 0..127
            const float* src = seg0 ? (B0 + (size_t)(bn + row) * DD + ca)
                                    : (B1 + (size_t)(bn + row) * ldb1 + ca);
            cpa16(Bb + row * 128 + ((ach ^ (row & 7)) * 16), src);
        }
        asm volatile("cp.async.commit_group;" ::: "memory");
    };

    const int warp = tid >> 5, lane = tid & 31;
    const int wm = warp & 3, wn = warp >> 2;
    const int lr = lane >> 2, lc = lane & 3;

    const int l7 = lane & 7;
    const int a_row_base = wm * 64 + ((lane >> 3) & 1) * 8 + l7;
    const int b_row_base = wn * 32 + (lane >> 4) * 8 + l7;
    const int a_chsel = (lane >> 4);
    const int b_chsel = ((lane >> 3) & 1);

    float c[4][4][4];
#pragma unroll
    for (int a = 0; a < 4; a++)
#pragma unroll
        for (int b = 0; b < 4; b++)
#pragma unroll
            for (int d = 0; d < 4; d++) c[a][b][d] = 0.f;

    issue(0);
    issue(1);
    issue(2);

    for (int kt = 0; kt < KT; kt++) {
        if (kt + 2 <= KT - 1)
            asm volatile("cp.async.wait_group 2;" ::: "memory");
        else if (kt + 1 <= KT - 1)
            asm volatile("cp.async.wait_group 1;" ::: "memory");
        else
            asm volatile("cp.async.wait_group 0;" ::: "memory");
        __syncthreads();

        if (kt + 3 < KT) issue(kt + 3);   // early issue: loads fly during MMAs

        const int s = kt & 3;
        const uint32_t Ab = sbase + s * AT_STAGE;
        const uint32_t Bb = Ab + 32768;
#pragma unroll
        for (int ks = 0; ks < 4; ks++) {
            uint32_t af[4][4];
#pragma unroll
            for (int mi = 0; mi < 4; mi++) {
                const int row = a_row_base + mi * 16;
                ldsm4(Ab + row * 128 + (((ks * 2 + a_chsel) ^ l7) * 16), af[mi]);
            }
            uint32_t bf[2][4];
#pragma unroll
            for (int np = 0; np < 2; np++) {
                const int row = b_row_base + np * 16;
                ldsm4(Bb + row * 128 + (((ks * 2 + b_chsel) ^ l7) * 16), bf[np]);
            }
#pragma unroll
            for (int np = 0; np < 2; np++)
#pragma unroll
                for (int sb = 0; sb < 2; sb++) {
                    const int ni = np * 2 + sb;
#pragma unroll
                    for (int mi = 0; mi < 4; mi++)
                        asm volatile(
                            "mma.sync.aligned.m16n8k8.row.col.f32.tf32.tf32.f32 "
                            "{%0,%1,%2,%3},{%4,%5,%6,%7},{%8,%9},{%0,%1,%2,%3};\n"
                            : "+f"(c[mi][ni][0]), "+f"(c[mi][ni][1]),
                              "+f"(c[mi][ni][2]), "+f"(c[mi][ni][3])
                            : "r"(af[mi][0]), "r"(af[mi][1]),
                              "r"(af[mi][2]), "r"(af[mi][3]),
                              "r"(bf[np][2 * sb]), "r"(bf[np][2 * sb + 1]));
                }
        }
    }

    // epilogue: bias + store (float2)
    float bl[4][2];
#pragma unroll
    for (int ni = 0; ni < 4; ni++) {
        const int col = bn + wn * 32 + ni * 8 + 2 * lc;
        bl[ni][0] = bc[(size_t)m * DIMF + col];
        bl[ni][1] = bc[(size_t)m * DIMF + col + 1];
    }
    float* Cm = att + (size_t)m * BSZ * DIMF;
#pragma unroll
    for (int mi = 0; mi < 4; mi++) {
        const int row = bm + wm * 64 + mi * 16 + lr;
#pragma unroll
        for (int ni = 0; ni < 4; ni++) {
            const int col = bn + wn * 32 + ni * 8 + 2 * lc;
            float2 v0 = make_float2(c[mi][ni][0] + bl[ni][0], c[mi][ni][1] + bl[ni][1]);
            float2 v1 = make_float2(c[mi][ni][2] + bl[ni][0], c[mi][ni][3] + bl[ni][1]);
            *(float2*)(Cm + (size_t)row * DIMF + col) = v0;
            *(float2*)(Cm + (size_t)(row + 8) * DIMF + col) = v1;
        }
    }
}

// ---------------- generic tf32 NT GEMM (mma.sync + ldmatrix) ----------------
template<int MODE, int RND>
__global__ __launch_bounds__(256, 2) void gemm2(
    const float* __restrict__ A0, long sA0z, int lda0, int K0,
    const float* __restrict__ A1, long sA1z, int lda1, int K1,
    const float* __restrict__ B0, long sB0z, int ldb0,
    const float* __restrict__ B1, long sB1z, int ldb1,
    const float* __restrict__ bias, long sBiasZ,
    const float* __restrict__ bng, const float* __restrict__ bnb,
    float* __restrict__ C, long sCz, int N)
{
    const int K  = K0 + K1;
    const int KT = K >> 5;

    extern __shared__ float sm[];
    float* As  = sm;
    float* Bsm = sm + 2 * 128 * 36;

    const int tid = threadIdx.x;
    const int z   = blockIdx.z;
    A0 += z * sA0z;
    if (A1) A1 += z * sA1z;
    B0 += z * sB0z;
    if (B1) B1 += z * sB1z;
    if (bias) bias += z * sBiasZ;
    C  += z * sCz;

    const int bm = blockIdx.y * 128;
    const int bn = blockIdx.x * 128;

    const int lrow = tid >> 3;
    const int c4   = (tid & 7) * 4;

    float4 a_stg[4], b_stg[4];

    auto ldTiles = [&](int kt) {
        const int gk = kt * 32 + c4;
#pragma unroll
        for (int i = 0; i < 4; i++) {
            const int row = lrow + i * 32;
            const float* s = (gk < K0) ? (A0 + (long)(bm + row) * lda0 + gk)
                                       : (A1 + (long)(bm + row) * lda1 + (gk - K0));
            a_stg[i] = *(const float4*)s;
        }
#pragma unroll
        for (int i = 0; i < 4; i++) {
            const int row = lrow + i * 32;
            int j = bn + row; if (j > N - 1) j = N - 1;
            const float* s = (gk < K0) ? (B0 + (long)j * ldb0 + gk)
                                       : (B1 + (long)j * ldb1 + (gk - K0));
            b_stg[i] = *(const float4*)s;
        }
    };
    auto stTiles = [&](int buf) {
        float* a = As  + buf * 128 * 36;
        float* b = Bsm + buf * 128 * 36;
#pragma unroll
        for (int i = 0; i < 4; i++)
            *(float4*)(a + (lrow + i * 32) * 36 + c4) = rnd4(a_stg[i]);
#pragma unroll
        for (int i = 0; i < 4; i++)
            *(float4*)(b + (lrow + i * 32) * 36 + c4) = rnd4(b_stg[i]);
    };

    float c[2][8][4];
#pragma unroll
    for (int a = 0; a < 2; a++)
#pragma unroll
        for (int b2 = 0; b2 < 8; b2++)
#pragma unroll
            for (int d = 0; d < 4; d++) c[a][b2][d] = 0.f;

    const int warp = tid >> 5, lane = tid & 31;
    const int wm = warp & 3, wn = warp >> 2;
    const int lr = lane >> 2, lc = lane & 3;

    const int a_row = wm * 32 + ((lane >> 3) & 1) * 8 + (lane & 7);
    const int a_col = (lane >> 4) * 4;
    const uint32_t aoff = (uint32_t)((a_row * 36 + a_col) * 4);
    const int b_row = wn * 64 + (lane >> 4) * 8 + (lane & 7);
    const int b_col = ((lane >> 3) & 1) * 4;
    const uint32_t boff = (uint32_t)((b_row * 36 + b_col) * 4);

    const uint32_t sA = (uint32_t)__cvta_generic_to_shared(As);
    const uint32_t sB = (uint32_t)__cvta_generic_to_shared(Bsm);
    const uint32_t BUF = 128 * 36 * 4;

    ldTiles(0);
    stTiles(0);
    __syncthreads();

    for (int kt = 0; kt < KT; kt++) {
        const bool has_next = (kt + 1 < KT);
        if (has_next) ldTiles(kt + 1);

        const uint32_t aBuf = sA + (kt & 1) * BUF + aoff;
        const uint32_t bBuf = sB + (kt & 1) * BUF + boff;
#pragma unroll
        for (int ks = 0; ks < 4; ks++) {
            const uint32_t kByte = (uint32_t)(ks * 8 * 4);
            uint32_t af[2][4];
#pragma unroll
            for (int mi = 0; mi < 2; mi++)
                ldsm4(aBuf + mi * (16 * 36 * 4) + kByte, af[mi]);
            uint32_t bf[4][4];
#pragma unroll
            for (int np = 0; np < 4; np++)
                ldsm4(bBuf + np * (16 * 36 * 4) + kByte, bf[np]);
#pragma unroll
            for (int np = 0; np < 4; np++)
#pragma unroll
                for (int s = 0; s < 2; s++) {
                    const int ni = np * 2 + s;
#pragma unroll
                    for (int mi = 0; mi < 2; mi++)
                        asm volatile(
                            "mma.sync.aligned.m16n8k8.row.col.f32.tf32.tf32.f32 "
                            "{%0,%1,%2,%3},{%4,%5,%6,%7},{%8,%9},{%0,%1,%2,%3};\n"
                            : "+f"(c[mi][ni][0]), "+f"(c[mi][ni][1]),
                              "+f"(c[mi][ni][2]), "+f"(c[mi][ni][3])
                            : "r"(af[mi][0]), "r"(af[mi][1]),
                              "r"(af[mi][2]), "r"(af[mi][3]),
                              "r"(bf[np][2 * s]), "r"(bf[np][2 * s + 1]));
                }
        }
        if (has_next) stTiles((kt + 1) & 1);
        __syncthreads();
    }

    const float inv = rsqrtf(1.0f + 1e-5f);
#pragma unroll
    for (int mi = 0; mi < 2; mi++) {
        const int row = bm + wm * 32 + mi * 16 + lr;
#pragma unroll
        for (int ni = 0; ni < 8; ni++) {
            const int col = bn + wn * 64 + ni * 8 + 2 * lc;
#pragma unroll
            for (int h = 0; h < 2; h++) {
                const int r = row + h * 8;
#pragma unroll
                for (int q = 0; q < 2; q++) {
                    const int j = col + q;
                    if (j < N) {
                        float v = c[mi][ni][h * 2 + q];
                        if (bias) v += bias[j];
                        if (MODE == 1) v = fmaxf(v, 0.f) * bng[j] * inv + bnb[j];
                        if (RND) v = rnd1(v);
                        C[(long)r * N + j] = v;
                    }
                }
            }
        }
    }
}

// ---------------- fea_u = sum over the 19 branches of x (float4) ----------------
__global__ void reduce_x(const float* __restrict__ x, float* __restrict__ out) {
    long idx = (long)blockIdx.x * blockDim.x + threadIdx.x;   // float4 index
    if (idx >= (long)BSZ * DIMF / 4) return;
    int b  = (int)(idx / (DIMF / 4));
    int d4 = (int)(idx % (DIMF / 4));
    const float4* p = (const float4*)(x + (size_t)b * XROW) + d4;
    float4 s = make_float4(0.f, 0.f, 0.f, 0.f);
#pragma unroll
    for (int mm = 0; mm < NBR; mm++) {
        float4 v = p[mm * (DIMF / 4)];
        s.x += v.x; s.y += v.y; s.z += v.z; s.w += v.w;
    }
    ((float4*)out)[idx] = s;
}

// ---------------- setup: transpose fcs_W  +  folded bias (merged) ----------------
__global__ void setup_misc(const float* __restrict__ fcsW, float* __restrict__ fcsT,
                           const float* __restrict__ gfcsW, const float* __restrict__ gfcsB,
                           const float* __restrict__ fcsB, float* __restrict__ bc)
{
    const int m = blockIdx.z;
    if (blockIdx.y < 12) {
        __shared__ float t[32][33];
        const int i0 = blockIdx.y * 32, d0 = blockIdx.x * 32;
        const float* src = fcsW + (size_t)m * DD * DD;
        float* dst       = fcsT + (size_t)m * DD * DD;
        const int x = threadIdx.x, y = threadIdx.y;
#pragma unroll
        for (int yy = y; yy < 32; yy += 8)
            t[yy][x] = src[(size_t)(i0 + yy) * DD + d0 + x];
        __syncthreads();
#pragma unroll
        for (int yy = y; yy < 32; yy += 8)
            dst[(size_t)(d0 + yy) * DD + i0 + x] = t[x][yy];
    } else {
        const int tid = threadIdx.y * 32 + threadIdx.x;
        const int w = tid >> 5, lane = tid & 31;
        const float* fb = fcsB + m * DD;
        for (int j = 0; j < 8; j++) {
            const int o = blockIdx.x * 64 + w * 8 + j;
            const float* wp = gfcsW + ((size_t)m * DIMF + o) * GW;
            float s = 0.f;
            for (int i = lane; i < DD; i += 32) s += wp[i] * fb[i];
#pragma unroll
            for (int off = 16; off; off >>= 1) s += __shfl_xor_sync(0xffffffffu, s, off);
            if (lane == 0) bc[(size_t)m * DIMF + o] = s + gfcsB[(size_t)m * DIMF + o];
        }
    }
}

// ---------------- softmax over m + weighted sum with x (float4) ----------------
__global__ void softmax_wsum(const float* __restrict__ att,
                             const float* __restrict__ x,
                             float* __restrict__ out) {
    long idx = (long)blockIdx.x * blockDim.x + threadIdx.x;   // float4 index
    if (idx >= (long)BSZ * DIMF / 4) return;
    int b  = (int)(idx / (DIMF / 4));
    int o4 = (int)(idx % (DIMF / 4));

    float4 v[NBR];
    float4 mx = make_float4(-1e30f, -1e30f, -1e30f, -1e30f);
#pragma unroll
    for (int mm = 0; mm < NBR; mm++) {
        v[mm] = *((const float4*)(att + ((size_t)mm * BSZ + b) * DIMF) + o4);
        mx.x = fmaxf(mx.x, v[mm].x); mx.y = fmaxf(mx.y, v[mm].y);
        mx.z = fmaxf(mx.z, v[mm].z); mx.w = fmaxf(mx.w, v[mm].w);
    }
    float4 s = make_float4(0.f, 0.f, 0.f, 0.f);
#pragma unroll
    for (int mm = 0; mm < NBR; mm++) {
        v[mm].x = __expf(v[mm].x - mx.x); s.x += v[mm].x;
        v[mm].y = __expf(v[mm].y - mx.y); s.y += v[mm].y;
        v[mm].z = __expf(v[mm].z - mx.z); s.z += v[mm].z;
        v[mm].w = __expf(v[mm].w - mx.w); s.w += v[mm].w;
    }
    s.x = 1.f / s.x; s.y = 1.f / s.y; s.z = 1.f / s.z; s.w = 1.f / s.w;
    float4 acc = make_float4(0.f, 0.f, 0.f, 0.f);
    const float4* xp = (const float4*)(x + (size_t)b * XROW) + o4;
#pragma unroll
    for (int mm = 0; mm < NBR; mm++) {
        float4 xv = xp[mm * (DIMF / 4)];
        acc.x += v[mm].x * s.x * xv.x;
        acc.y += v[mm].y * s.y * xv.y;
        acc.z += v[mm].z * s.z * xv.z;
        acc.w += v[mm].w * s.w * xv.w;
    }
    ((float4*)out)[idx] = acc;
}

// ---------------- launch ----------------
extern "C" void kernel_launch(void* const* d_in, const int* in_sizes, int n_in,
                              void* d_out, int out_size) {
    const float* x      = (const float*)d_in[0];
    const float* g      = (const float*)d_in[1];
    const float* fc1_W  = (const float*)d_in[2];
    const float* fc1_b  = (const float*)d_in[3];
    const float* bn1_g  = (const float*)d_in[4];
    const float* bn1_b  = (const float*)d_in[5];
    const float* fc2_W  = (const float*)d_in[6];
    const float* fc2_b  = (const float*)d_in[7];
    const float* fcs_W  = (const float*)d_in[8];
    const float* fcs_b  = (const float*)d_in[9];
    const float* gfcs_W = (const float*)d_in[10];
    const float* gfcs_b = (const float*)d_in[11];
    const float* l1_W   = (const float*)d_in[12];
    const float* l1_b   = (const float*)d_in[13];
    const float* bna_g  = (const float*)d_in[14];
    const float* bna_b  = (const float*)d_in[15];
    const float* l2_W   = (const float*)d_in[16];
    const float* l2_b   = (const float*)d_in[17];
    const float* bnb_g  = (const float*)d_in[18];
    const float* bnb_b  = (const float*)d_in[19];
    const float* l3_W   = (const float*)d_in[20];
    const float* l3_b   = (const float*)d_in[21];
    float* out = (float*)d_out;

    float *fea_u, *h1, *fea_z, *att, *fea_v, *hA, *hB, *Wc, *fcsT, *bc;
    cudaGetSymbolAddress((void**)&fea_u, g_fea_u);
    cudaGetSymbolAddress((void**)&h1,    g_h1);
    cudaGetSymbolAddress((void**)&fea_z, g_fea_z);
    cudaGetSymbolAddress((void**)&att,   g_att);
    cudaGetSymbolAddress((void**)&fea_v, g_fea_v);
    cudaGetSymbolAddress((void**)&hA,    g_hA);
    cudaGetSymbolAddress((void**)&hB,    g_hB);
    cudaGetSymbolAddress((void**)&Wc,    g_Wc);
    cudaGetSymbolAddress((void**)&fcsT,  g_fcsT);
    cudaGetSymbolAddress((void**)&bc,    g_bc);

    const int SMEM  = 2 * 2 * 128 * 36 * 4;   // gemm2: 73728 B
    const int ASMEM = 4 * AT_STAGE;           // att_cp: 196608 B
    cudaFuncSetAttribute(gemm2<0,0>, cudaFuncAttributeMaxDynamicSharedMemorySize, SMEM);
    cudaFuncSetAttribute(gemm2<0,1>, cudaFuncAttributeMaxDynamicSharedMemorySize, SMEM);
    cudaFuncSetAttribute(gemm2<1,0>, cudaFuncAttributeMaxDynamicSharedMemorySize, SMEM);
    cudaFuncSetAttribute(att_cp,     cudaFuncAttributeMaxDynamicSharedMemorySize, ASMEM);

    // ---- fork a side stream for the weight-prep branch (graph-capture legal) ----
    cudaStream_t s2;
    cudaStreamCreateWithFlags(&s2, cudaStreamNonBlocking);
    cudaEvent_t e0, e1;
    cudaEventCreateWithFlags(&e0, cudaEventDisableTiming);
    cudaEventCreateWithFlags(&e1, cudaEventDisableTiming);

    cudaEventRecord(e0, 0);
    cudaStreamWaitEvent(s2, e0, 0);

    // --- branch S2: weight prep (setup_misc -> Wc fold) ---
    setup_misc<<<dim3(12, 13, NBR), dim3(32, 8), 0, s2>>>(fcs_W, fcsT, gfcs_W, gfcs_b, fcs_b, bc);
    gemm2<0,1><<<dim3(3, 6, NBR), 256, SMEM, s2>>>(
        gfcs_W, (long)DIMF * GW, GW, DD,  nullptr, 0, 0, 0,
        fcsT, (long)DD * DD, DD,  nullptr, 0, 0,
        nullptr, 0, nullptr, nullptr,
        Wc, (long)DIMF * DD, DD);
    cudaEventRecord(e1, s2);

    // --- main stream: activation chain ---
    reduce_x<<<(BSZ * DIMF / 4 + 255) / 256, 256>>>(x, fea_u);

    gemm2<1,0><<<dim3(3, 32, 1), 256, SMEM>>>(
        fea_u, 0, DIMF, DIMF,  nullptr, 0, 0, 0,
        fc1_W, 0, DIMF,  nullptr, 0, 0,
        fc1_b, 0, bn1_g, bn1_b, h1, 0, DD);

    gemm2<0,1><<<dim3(3, 32, 1), 256, SMEM>>>(
        h1, 0, DD, DD,  nullptr, 0, 0, 0,
        fc2_W, 0, DD,  nullptr, 0, 0,
        fc2_b, 0, nullptr, nullptr, fea_z, 0, DD);

    // join: att needs Wc/bc from s2
    cudaStreamWaitEvent(0, e1, 0);

    // att (cp.async pipelined tensor GEMM; g and gfcsB slice read raw)
    att_cp<<<dim3(6, 16, NBR), 512, ASMEM>>>(fea_z, g, Wc, gfcs_W + DD, GW, bc, att);

    // softmax over m + weighted sum with x
    softmax_wsum<<<(BSZ * DIMF / 4 + 255) / 256, 256>>>(att, x, fea_v);

    // classifier head
    gemm2<1,0><<<dim3(1, 32, 1), 256, SMEM>>>(
        fea_v, 0, DIMF, DIMF,  nullptr, 0, 0, 0,
        l1_W, 0, DIMF,  nullptr, 0, 0,
        l1_b, 0, bna_g, bna_b, hA, 0, 128);

    gemm2<1,0><<<dim3(1, 32, 1), 256, SMEM>>>(
        hA, 0, 128, 128,  nullptr, 0, 0, 0,
        l2_W, 0, 128,  nullptr, 0, 0,
        l2_b, 0, bnb_g, bnb_b, hB, 0, 32);

    gemm2<0,0><<<dim3(1, 32, 1), 256, SMEM>>>(
        hB, 0, 32, 32,  nullptr, 0, 0, 0,
        l3_W, 0, 32,  nullptr, 0, 0,
        l3_b, 0, nullptr, nullptr, out, 0, 20);

    cudaEventDestroy(e0);
    cudaEventDestroy(e1);
    cudaStreamDestroy(s2);
}

// round 11
// speedup vs baseline: 1.5055x; 1.0055x over previous
#include <cuda_runtime.h>
#include <cstdint>

#define NBR   19
#define DIMF  768
#define DD    384
#define BSZ   4096
#define XROW  (NBR * DIMF)   // 14592
#define GW    (DIMF + DD)    // 1152

// ---------------- scratch (device globals) ----------------
__device__ float g_fea_u[(size_t)BSZ * DIMF];
__device__ float g_h1[(size_t)BSZ * DD];
__device__ float g_fea_z[(size_t)BSZ * DD];
__device__ float g_att[(size_t)NBR * BSZ * DIMF];
__device__ float g_fea_v[(size_t)BSZ * DIMF];
__device__ float g_hA[(size_t)BSZ * 128];
__device__ float g_hB[(size_t)BSZ * 32];
__device__ float g_Wc[(size_t)NBR * DIMF * DD];
__device__ float g_fcsT[(size_t)NBR * DD * DD];
__device__ float g_bc[(size_t)NBR * DIMF];

// ---------------- helpers ----------------
__device__ __forceinline__ uint32_t f2tf32(float x) {
    uint32_t u;
    asm("cvt.rna.tf32.f32 %0, %1;" : "=r"(u) : "f"(x));
    return u;
}
__device__ __forceinline__ float rnd1(float x) { return __uint_as_float(f2tf32(x)); }
__device__ __forceinline__ float4 rnd4(float4 v) {
    v.x = rnd1(v.x); v.y = rnd1(v.y); v.z = rnd1(v.z); v.w = rnd1(v.w);
    return v;
}
__device__ __forceinline__ void ldsm4(uint32_t a, uint32_t r[4]) {
    asm volatile("ldmatrix.sync.aligned.m8n8.x4.shared.b16 {%0,%1,%2,%3}, [%4];"
                 : "=r"(r[0]), "=r"(r[1]), "=r"(r[2]), "=r"(r[3]) : "r"(a));
}
__device__ __forceinline__ void cpa16(uint32_t dst, const void* src) {
    asm volatile("cp.async.cg.shared.global [%0], [%1], 16;" :: "r"(dst), "l"(src));
}

// =====================================================================
// att_cp: att[m][b][o] = sum_k A[b][k]*B[o][k] + bc[m][o]
//   A = [fea_z (384, RNA-rounded) | g[:,m,:] (768, raw -> HW truncation)]
//   B = [Wc[m] (384, rounded) | gfcsB slice of gfcs_W (768, raw -> HW truncation)]
// Tile 256x128x32, 512 threads (warps 4x4, warp tile 64x32),
// 4-stage cp.async pipeline, XOR-swizzled 128B smem rows, ldmatrix feeds.
// =====================================================================
#define AT_STAGE 49152          // 32768 (A) + 16384 (B) bytes per stage
__global__ __launch_bounds__(512) void att_cp(
    const float* __restrict__ fea_z,
    const float* __restrict__ g,
    const float* __restrict__ Wc,
    const float* __restrict__ WB,      // row stride ldb1
    int ldb1,
    const float* __restrict__ bc,
    float* __restrict__ att)
{
    extern __shared__ char smraw[];
    const uint32_t sbase = (uint32_t)__cvta_generic_to_shared(smraw);
    const int tid = threadIdx.x;
    const int m  = blockIdx.z;
    const int bm = blockIdx.y * 256;
    const int bn = blockIdx.x * 128;

    const float* A1 = g + (size_t)m * DIMF;
    const float* B0 = Wc + (size_t)m * DIMF * DD;
    const float* B1 = WB + (size_t)m * DIMF * ldb1;

    const int arow = tid >> 3;          // A rows at +0,+64,+128,+192
    const int ach  = tid & 7;           // 16B chunk within 128B row
    const int KT = GW / 32;             // 36

    auto issue = [&](int kt) {
        const int s = kt & 3;
        const uint32_t Ab = sbase + s * AT_STAGE;
        const uint32_t Bb = Ab + 32768;
        const int kb = kt * 32;
        const bool seg0 = kb < DD;
        const int ca = seg0 ? (kb + ach * 4) : (kb - DD + ach * 4);
#pragma unroll
        for (int i = 0; i < 4; i++) {
            const int row = arow + i * 64;
            const float* src = seg0 ? (fea_z + (size_t)(bm + row) * DD + ca)
                                    : (A1 + (size_t)(bm + row) * XROW + ca);
            cpa16(Ab + row * 128 + ((ach ^ (row & 7)) * 16), src);
        }
#pragma unroll
        for (int i = 0; i < 2; i++) {
            const int row = (tid >> 3) + i * 64;   // 0..127
            const float* src = seg0 ? (B0 + (size_t)(bn + row) * DD + ca)
                                    : (B1 + (size_t)(bn + row) * ldb1 + ca);
            cpa16(Bb + row * 128 + ((ach ^ (row & 7)) * 16), src);
        }
        asm volatile("cp.async.commit_group;" ::: "memory");
    };

    const int warp = tid >> 5, lane = tid & 31;
    const int wm = warp & 3, wn = warp >> 2;
    const int lr = lane >> 2, lc = lane & 3;

    const int l7 = lane & 7;
    const int a_row_base = wm * 64 + ((lane >> 3) & 1) * 8 + l7;
    const int b_row_base = wn * 32 + (lane >> 4) * 8 + l7;
    const int a_chsel = (lane >> 4);
    const int b_chsel = ((lane >> 3) & 1);

    float c[4][4][4];
#pragma unroll
    for (int a = 0; a < 4; a++)
#pragma unroll
        for (int b = 0; b < 4; b++)
#pragma unroll
            for (int d = 0; d < 4; d++) c[a][b][d] = 0.f;

    issue(0);
    issue(1);
    issue(2);

    for (int kt = 0; kt < KT; kt++) {
        if (kt + 2 <= KT - 1)
            asm volatile("cp.async.wait_group 2;" ::: "memory");
        else if (kt + 1 <= KT - 1)
            asm volatile("cp.async.wait_group 1;" ::: "memory");
        else
            asm volatile("cp.async.wait_group 0;" ::: "memory");
        __syncthreads();

        if (kt + 3 < KT) issue(kt + 3);   // early issue: loads fly during MMAs

        const int s = kt & 3;
        const uint32_t Ab = sbase + s * AT_STAGE;
        const uint32_t Bb = Ab + 32768;
#pragma unroll
        for (int ks = 0; ks < 4; ks++) {
            uint32_t af[4][4];
#pragma unroll
            for (int mi = 0; mi < 4; mi++) {
                const int row = a_row_base + mi * 16;
                ldsm4(Ab + row * 128 + (((ks * 2 + a_chsel) ^ l7) * 16), af[mi]);
            }
            uint32_t bf[2][4];
#pragma unroll
            for (int np = 0; np < 2; np++) {
                const int row = b_row_base + np * 16;
                ldsm4(Bb + row * 128 + (((ks * 2 + b_chsel) ^ l7) * 16), bf[np]);
            }
#pragma unroll
            for (int np = 0; np < 2; np++)
#pragma unroll
                for (int sb = 0; sb < 2; sb++) {
                    const int ni = np * 2 + sb;
#pragma unroll
                    for (int mi = 0; mi < 4; mi++)
                        asm volatile(
                            "mma.sync.aligned.m16n8k8.row.col.f32.tf32.tf32.f32 "
                            "{%0,%1,%2,%3},{%4,%5,%6,%7},{%8,%9},{%0,%1,%2,%3};\n"
                            : "+f"(c[mi][ni][0]), "+f"(c[mi][ni][1]),
                              "+f"(c[mi][ni][2]), "+f"(c[mi][ni][3])
                            : "r"(af[mi][0]), "r"(af[mi][1]),
                              "r"(af[mi][2]), "r"(af[mi][3]),
                              "r"(bf[np][2 * sb]), "r"(bf[np][2 * sb + 1]));
                }
        }
    }

    // epilogue: bias + store (float2)
    float bl[4][2];
#pragma unroll
    for (int ni = 0; ni < 4; ni++) {
        const int col = bn + wn * 32 + ni * 8 + 2 * lc;
        bl[ni][0] = bc[(size_t)m * DIMF + col];
        bl[ni][1] = bc[(size_t)m * DIMF + col + 1];
    }
    float* Cm = att + (size_t)m * BSZ * DIMF;
#pragma unroll
    for (int mi = 0; mi < 4; mi++) {
        const int row = bm + wm * 64 + mi * 16 + lr;
#pragma unroll
        for (int ni = 0; ni < 4; ni++) {
            const int col = bn + wn * 32 + ni * 8 + 2 * lc;
            float2 v0 = make_float2(c[mi][ni][0] + bl[ni][0], c[mi][ni][1] + bl[ni][1]);
            float2 v1 = make_float2(c[mi][ni][2] + bl[ni][0], c[mi][ni][3] + bl[ni][1]);
            *(float2*)(Cm + (size_t)row * DIMF + col) = v0;
            *(float2*)(Cm + (size_t)(row + 8) * DIMF + col) = v1;
        }
    }
}

// ---------------- generic tf32 NT GEMM (mma.sync + ldmatrix) ----------------
// MI: M-tile = MI*64 rows (MI=2 -> 128x128 tile, MI=1 -> 64x128 tile).
// Accumulation order per output element is identical across MI values.
template<int MODE, int RND, int MI>
__global__ __launch_bounds__(256, 2) void gemm2(
    const float* __restrict__ A0, long sA0z, int lda0, int K0,
    const float* __restrict__ A1, long sA1z, int lda1, int K1,
    const float* __restrict__ B0, long sB0z, int ldb0,
    const float* __restrict__ B1, long sB1z, int ldb1,
    const float* __restrict__ bias, long sBiasZ,
    const float* __restrict__ bng, const float* __restrict__ bnb,
    float* __restrict__ C, long sCz, int N)
{
    const int K  = K0 + K1;
    const int KT = K >> 5;
    constexpr int MROWS = MI * 64;

    extern __shared__ float sm[];
    float* As  = sm;                        // [2][MROWS][36]
    float* Bsm = sm + 2 * MROWS * 36;       // [2][128][36]

    const int tid = threadIdx.x;
    const int z   = blockIdx.z;
    A0 += z * sA0z;
    if (A1) A1 += z * sA1z;
    B0 += z * sB0z;
    if (B1) B1 += z * sB1z;
    if (bias) bias += z * sBiasZ;
    C  += z * sCz;

    const int bm = blockIdx.y * MROWS;
    const int bn = blockIdx.x * 128;

    const int lrow = tid >> 3;
    const int c4   = (tid & 7) * 4;

    float4 a_stg[2 * MI], b_stg[4];

    auto ldTiles = [&](int kt) {
        const int gk = kt * 32 + c4;
#pragma unroll
        for (int i = 0; i < 2 * MI; i++) {
            const int row = lrow + i * 32;
            const float* s = (gk < K0) ? (A0 + (long)(bm + row) * lda0 + gk)
                                       : (A1 + (long)(bm + row) * lda1 + (gk - K0));
            a_stg[i] = *(const float4*)s;
        }
#pragma unroll
        for (int i = 0; i < 4; i++) {
            const int row = lrow + i * 32;
            int j = bn + row; if (j > N - 1) j = N - 1;
            const float* s = (gk < K0) ? (B0 + (long)j * ldb0 + gk)
                                       : (B1 + (long)j * ldb1 + (gk - K0));
            b_stg[i] = *(const float4*)s;
        }
    };
    auto stTiles = [&](int buf) {
        float* a = As  + buf * MROWS * 36;
        float* b = Bsm + buf * 128 * 36;
#pragma unroll
        for (int i = 0; i < 2 * MI; i++)
            *(float4*)(a + (lrow + i * 32) * 36 + c4) = rnd4(a_stg[i]);
#pragma unroll
        for (int i = 0; i < 4; i++)
            *(float4*)(b + (lrow + i * 32) * 36 + c4) = rnd4(b_stg[i]);
    };

    float c[MI][8][4];
#pragma unroll
    for (int a = 0; a < MI; a++)
#pragma unroll
        for (int b2 = 0; b2 < 8; b2++)
#pragma unroll
            for (int d = 0; d < 4; d++) c[a][b2][d] = 0.f;

    const int warp = tid >> 5, lane = tid & 31;
    const int wm = warp & 3, wn = warp >> 2;
    const int lr = lane >> 2, lc = lane & 3;

    const int a_row = wm * (MI * 16) + ((lane >> 3) & 1) * 8 + (lane & 7);
    const int a_col = (lane >> 4) * 4;
    const uint32_t aoff = (uint32_t)((a_row * 36 + a_col) * 4);
    const int b_row = wn * 64 + (lane >> 4) * 8 + (lane & 7);
    const int b_col = ((lane >> 3) & 1) * 4;
    const uint32_t boff = (uint32_t)((b_row * 36 + b_col) * 4);

    const uint32_t sA = (uint32_t)__cvta_generic_to_shared(As);
    const uint32_t sB = (uint32_t)__cvta_generic_to_shared(Bsm);
    const uint32_t ABUF = MROWS * 36 * 4;
    const uint32_t BBUF = 128 * 36 * 4;

    ldTiles(0);
    stTiles(0);
    __syncthreads();

    for (int kt = 0; kt < KT; kt++) {
        const bool has_next = (kt + 1 < KT);
        if (has_next) ldTiles(kt + 1);

        const uint32_t aBuf = sA + (kt & 1) * ABUF + aoff;
        const uint32_t bBuf = sB + (kt & 1) * BBUF + boff;
#pragma unroll
        for (int ks = 0; ks < 4; ks++) {
            const uint32_t kByte = (uint32_t)(ks * 8 * 4);
            uint32_t af[MI][4];
#pragma unroll
            for (int mi = 0; mi < MI; mi++)
                ldsm4(aBuf + mi * (16 * 36 * 4) + kByte, af[mi]);
            uint32_t bf[4][4];
#pragma unroll
            for (int np = 0; np < 4; np++)
                ldsm4(bBuf + np * (16 * 36 * 4) + kByte, bf[np]);
#pragma unroll
            for (int np = 0; np < 4; np++)
#pragma unroll
                for (int s = 0; s < 2; s++) {
                    const int ni = np * 2 + s;
#pragma unroll
                    for (int mi = 0; mi < MI; mi++)
                        asm volatile(
                            "mma.sync.aligned.m16n8k8.row.col.f32.tf32.tf32.f32 "
                            "{%0,%1,%2,%3},{%4,%5,%6,%7},{%8,%9},{%0,%1,%2,%3};\n"
                            : "+f"(c[mi][ni][0]), "+f"(c[mi][ni][1]),
                              "+f"(c[mi][ni][2]), "+f"(c[mi][ni][3])
                            : "r"(af[mi][0]), "r"(af[mi][1]),
                              "r"(af[mi][2]), "r"(af[mi][3]),
                              "r"(bf[np][2 * s]), "r"(bf[np][2 * s + 1]));
                }
        }
        if (has_next) stTiles((kt + 1) & 1);
        __syncthreads();
    }

    const float inv = rsqrtf(1.0f + 1e-5f);
#pragma unroll
    for (int mi = 0; mi < MI; mi++) {
        const int row = bm + wm * (MI * 16) + mi * 16 + lr;
#pragma unroll
        for (int ni = 0; ni < 8; ni++) {
            const int col = bn + wn * 64 + ni * 8 + 2 * lc;
#pragma unroll
            for (int h = 0; h < 2; h++) {
                const int r = row + h * 8;
#pragma unroll
                for (int q = 0; q < 2; q++) {
                    const int j = col + q;
                    if (j < N) {
                        float v = c[mi][ni][h * 2 + q];
                        if (bias) v += bias[j];
                        if (MODE == 1) v = fmaxf(v, 0.f) * bng[j] * inv + bnb[j];
                        if (RND) v = rnd1(v);
                        C[(long)r * N + j] = v;
                    }
                }
            }
        }
    }
}

// ---------------- fea_u = sum over the 19 branches of x (float4) ----------------
__global__ void reduce_x(const float* __restrict__ x, float* __restrict__ out) {
    long idx = (long)blockIdx.x * blockDim.x + threadIdx.x;   // float4 index
    if (idx >= (long)BSZ * DIMF / 4) return;
    int b  = (int)(idx / (DIMF / 4));
    int d4 = (int)(idx % (DIMF / 4));
    const float4* p = (const float4*)(x + (size_t)b * XROW) + d4;
    float4 s = make_float4(0.f, 0.f, 0.f, 0.f);
#pragma unroll
    for (int mm = 0; mm < NBR; mm++) {
        float4 v = p[mm * (DIMF / 4)];
        s.x += v.x; s.y += v.y; s.z += v.z; s.w += v.w;
    }
    ((float4*)out)[idx] = s;
}

// ---------------- setup: transpose fcs_W  +  folded bias (merged) ----------------
__global__ void setup_misc(const float* __restrict__ fcsW, float* __restrict__ fcsT,
                           const float* __restrict__ gfcsW, const float* __restrict__ gfcsB,
                           const float* __restrict__ fcsB, float* __restrict__ bc)
{
    const int m = blockIdx.z;
    if (blockIdx.y < 12) {
        __shared__ float t[32][33];
        const int i0 = blockIdx.y * 32, d0 = blockIdx.x * 32;
        const float* src = fcsW + (size_t)m * DD * DD;
        float* dst       = fcsT + (size_t)m * DD * DD;
        const int x = threadIdx.x, y = threadIdx.y;
#pragma unroll
        for (int yy = y; yy < 32; yy += 8)
            t[yy][x] = src[(size_t)(i0 + yy) * DD + d0 + x];
        __syncthreads();
#pragma unroll
        for (int yy = y; yy < 32; yy += 8)
            dst[(size_t)(d0 + yy) * DD + i0 + x] = t[x][yy];
    } else {
        const int tid = threadIdx.y * 32 + threadIdx.x;
        const int w = tid >> 5, lane = tid & 31;
        const float* fb = fcsB + m * DD;
        for (int j = 0; j < 8; j++) {
            const int o = blockIdx.x * 64 + w * 8 + j;
            const float* wp = gfcsW + ((size_t)m * DIMF + o) * GW;
            float s = 0.f;
            for (int i = lane; i < DD; i += 32) s += wp[i] * fb[i];
#pragma unroll
            for (int off = 16; off; off >>= 1) s += __shfl_xor_sync(0xffffffffu, s, off);
            if (lane == 0) bc[(size_t)m * DIMF + o] = s + gfcsB[(size_t)m * DIMF + o];
        }
    }
}

// ---------------- softmax over m + weighted sum with x (float4) ----------------
__global__ void softmax_wsum(const float* __restrict__ att,
                             const float* __restrict__ x,
                             float* __restrict__ out) {
    long idx = (long)blockIdx.x * blockDim.x + threadIdx.x;   // float4 index
    if (idx >= (long)BSZ * DIMF / 4) return;
    int b  = (int)(idx / (DIMF / 4));
    int o4 = (int)(idx % (DIMF / 4));

    float4 v[NBR];
    float4 mx = make_float4(-1e30f, -1e30f, -1e30f, -1e30f);
#pragma unroll
    for (int mm = 0; mm < NBR; mm++) {
        v[mm] = *((const float4*)(att + ((size_t)mm * BSZ + b) * DIMF) + o4);
        mx.x = fmaxf(mx.x, v[mm].x); mx.y = fmaxf(mx.y, v[mm].y);
        mx.z = fmaxf(mx.z, v[mm].z); mx.w = fmaxf(mx.w, v[mm].w);
    }
    float4 s = make_float4(0.f, 0.f, 0.f, 0.f);
#pragma unroll
    for (int mm = 0; mm < NBR; mm++) {
        v[mm].x = __expf(v[mm].x - mx.x); s.x += v[mm].x;
        v[mm].y = __expf(v[mm].y - mx.y); s.y += v[mm].y;
        v[mm].z = __expf(v[mm].z - mx.z); s.z += v[mm].z;
        v[mm].w = __expf(v[mm].w - mx.w); s.w += v[mm].w;
    }
    s.x = 1.f / s.x; s.y = 1.f / s.y; s.z = 1.f / s.z; s.w = 1.f / s.w;
    float4 acc = make_float4(0.f, 0.f, 0.f, 0.f);
    const float4* xp = (const float4*)(x + (size_t)b * XROW) + o4;
#pragma unroll
    for (int mm = 0; mm < NBR; mm++) {
        float4 xv = xp[mm * (DIMF / 4)];
        acc.x += v[mm].x * s.x * xv.x;
        acc.y += v[mm].y * s.y * xv.y;
        acc.z += v[mm].z * s.z * xv.z;
        acc.w += v[mm].w * s.w * xv.w;
    }
    ((float4*)out)[idx] = acc;
}

// ---------------- launch ----------------
extern "C" void kernel_launch(void* const* d_in, const int* in_sizes, int n_in,
                              void* d_out, int out_size) {
    const float* x      = (const float*)d_in[0];
    const float* g      = (const float*)d_in[1];
    const float* fc1_W  = (const float*)d_in[2];
    const float* fc1_b  = (const float*)d_in[3];
    const float* bn1_g  = (const float*)d_in[4];
    const float* bn1_b  = (const float*)d_in[5];
    const float* fc2_W  = (const float*)d_in[6];
    const float* fc2_b  = (const float*)d_in[7];
    const float* fcs_W  = (const float*)d_in[8];
    const float* fcs_b  = (const float*)d_in[9];
    const float* gfcs_W = (const float*)d_in[10];
    const float* gfcs_b = (const float*)d_in[11];
    const float* l1_W   = (const float*)d_in[12];
    const float* l1_b   = (const float*)d_in[13];
    const float* bna_g  = (const float*)d_in[14];
    const float* bna_b  = (const float*)d_in[15];
    const float* l2_W   = (const float*)d_in[16];
    const float* l2_b   = (const float*)d_in[17];
    const float* bnb_g  = (const float*)d_in[18];
    const float* bnb_b  = (const float*)d_in[19];
    const float* l3_W   = (const float*)d_in[20];
    const float* l3_b   = (const float*)d_in[21];
    float* out = (float*)d_out;

    float *fea_u, *h1, *fea_z, *att, *fea_v, *hA, *hB, *Wc, *fcsT, *bc;
    cudaGetSymbolAddress((void**)&fea_u, g_fea_u);
    cudaGetSymbolAddress((void**)&h1,    g_h1);
    cudaGetSymbolAddress((void**)&fea_z, g_fea_z);
    cudaGetSymbolAddress((void**)&att,   g_att);
    cudaGetSymbolAddress((void**)&fea_v, g_fea_v);
    cudaGetSymbolAddress((void**)&hA,    g_hA);
    cudaGetSymbolAddress((void**)&hB,    g_hB);
    cudaGetSymbolAddress((void**)&Wc,    g_Wc);
    cudaGetSymbolAddress((void**)&fcsT,  g_fcsT);
    cudaGetSymbolAddress((void**)&bc,    g_bc);

    const int SMEM2  = 2 * (128 + 128) * 36 * 4;   // MI=2: 73728 B
    const int SMEM1  = 2 * (64 + 128) * 36 * 4;    // MI=1: 55296 B
    const int ASMEM  = 4 * AT_STAGE;               // att_cp: 196608 B
    cudaFuncSetAttribute(gemm2<0,0,1>, cudaFuncAttributeMaxDynamicSharedMemorySize, SMEM1);
    cudaFuncSetAttribute(gemm2<0,1,1>, cudaFuncAttributeMaxDynamicSharedMemorySize, SMEM1);
    cudaFuncSetAttribute(gemm2<1,0,1>, cudaFuncAttributeMaxDynamicSharedMemorySize, SMEM1);
    cudaFuncSetAttribute(gemm2<0,1,2>, cudaFuncAttributeMaxDynamicSharedMemorySize, SMEM2);
    cudaFuncSetAttribute(att_cp,       cudaFuncAttributeMaxDynamicSharedMemorySize, ASMEM);

    // ---- fork a side stream for the weight-prep branch (graph-capture legal) ----
    cudaStream_t s2;
    cudaStreamCreateWithFlags(&s2, cudaStreamNonBlocking);
    cudaEvent_t e0, e1;
    cudaEventCreateWithFlags(&e0, cudaEventDisableTiming);
    cudaEventCreateWithFlags(&e1, cudaEventDisableTiming);

    cudaEventRecord(e0, 0);
    cudaStreamWaitEvent(s2, e0, 0);

    // --- branch S2: weight prep (setup_misc -> Wc fold) ---
    setup_misc<<<dim3(12, 13, NBR), dim3(32, 8), 0, s2>>>(fcs_W, fcsT, gfcs_W, gfcs_b, fcs_b, bc);
    gemm2<0,1,2><<<dim3(3, 6, NBR), 256, SMEM2, s2>>>(
        gfcs_W, (long)DIMF * GW, GW, DD,  nullptr, 0, 0, 0,
        fcsT, (long)DD * DD, DD,  nullptr, 0, 0,
        nullptr, 0, nullptr, nullptr,
        Wc, (long)DIMF * DD, DD);
    cudaEventRecord(e1, s2);

    // --- main stream: activation chain (MI=1 tiles for occupancy) ---
    reduce_x<<<(BSZ * DIMF / 4 + 255) / 256, 256>>>(x, fea_u);

    gemm2<1,0,1><<<dim3(3, 64, 1), 256, SMEM1>>>(
        fea_u, 0, DIMF, DIMF,  nullptr, 0, 0, 0,
        fc1_W, 0, DIMF,  nullptr, 0, 0,
        fc1_b, 0, bn1_g, bn1_b, h1, 0, DD);

    gemm2<0,1,1><<<dim3(3, 64, 1), 256, SMEM1>>>(
        h1, 0, DD, DD,  nullptr, 0, 0, 0,
        fc2_W, 0, DD,  nullptr, 0, 0,
        fc2_b, 0, nullptr, nullptr, fea_z, 0, DD);

    // join: att needs Wc/bc from s2
    cudaStreamWaitEvent(0, e1, 0);

    // att (cp.async pipelined tensor GEMM; g and gfcsB slice read raw)
    att_cp<<<dim3(6, 16, NBR), 512, ASMEM>>>(fea_z, g, Wc, gfcs_W + DD, GW, bc, att);

    // softmax over m + weighted sum with x
    softmax_wsum<<<(BSZ * DIMF / 4 + 255) / 256, 256>>>(att, x, fea_v);

    // classifier head (MI=1 tiles)
    gemm2<1,0,1><<<dim3(1, 64, 1), 256, SMEM1>>>(
        fea_v, 0, DIMF, DIMF,  nullptr, 0, 0, 0,
        l1_W, 0, DIMF,  nullptr, 0, 0,
        l1_b, 0, bna_g, bna_b, hA, 0, 128);

    gemm2<1,0,1><<<dim3(1, 64, 1), 256, SMEM1>>>(
        hA, 0, 128, 128,  nullptr, 0, 0, 0,
        l2_W, 0, 128,  nullptr, 0, 0,
        l2_b, 0, bnb_g, bnb_b, hB, 0, 32);

    gemm2<0,0,1><<<dim3(1, 64, 1), 256, SMEM1>>>(
        hB, 0, 32, 32,  nullptr, 0, 0, 0,
        l3_W, 0, 32,  nullptr, 0, 0,
        l3_b, 0, nullptr, nullptr, out, 0, 20);

    cudaEventDestroy(e0);
    cudaEventDestroy(e1);
    cudaStreamDestroy(s2);
}